// round 2
// baseline (speedup 1.0000x reference)
#include <cuda_runtime.h>
#include <mma.h>
#include <cstdint>

using namespace nvcuda;

#define D_MODEL 768
#define HEADS   12
#define D_HEAD  64
#define NB      16
#define SP      256
#define SI      1024
#define TOKP    (NB*SP)     /* 4096  */
#define TOKI    (NB*SI)     /* 16384 */

// ---------------- scratch (device globals: no allocations allowed) ----------------
__device__ float g_prompt0[TOKP*D_MODEL];
__device__ float g_x      [TOKP*D_MODEL];
__device__ float g_xi     [TOKI*D_MODEL];
__device__ float g_q      [TOKP*D_MODEL];
__device__ float g_k      [TOKI*D_MODEL];
__device__ float g_v      [TOKI*D_MODEL];
__device__ float g_scores [(size_t)NB*HEADS*SP*SI];
__device__ float g_attn   [TOKP*D_MODEL];
__device__ float g_p1     [TOKP*D_MODEL];
__device__ float g_p2     [TOKP*D_MODEL];
__device__ float g_h      [TOKP*D_MODEL];

// ---------------- cp.async helpers ----------------
__device__ __forceinline__ void cp16(float* s, const float* g) {
    uint32_t sa = (uint32_t)__cvta_generic_to_shared(s);
    asm volatile("cp.async.cg.shared.global [%0], [%1], 16;" :: "r"(sa), "l"(g));
}
__device__ __forceinline__ void cp_commit() { asm volatile("cp.async.commit_group;"); }

// ---------------- elementwise add (float4) ----------------
__global__ void add4_kernel(const float4* __restrict__ a, const float4* __restrict__ b,
                            float4* __restrict__ o, int n4) {
    int i = blockIdx.x * blockDim.x + threadIdx.x;
    if (i < n4) {
        float4 x = a[i], y = b[i];
        x.x += y.x; x.y += y.y; x.z += y.z; x.w += y.w;
        o[i] = x;
    }
}

// ---------------- (optional add) + layernorm, one row (768) per block of 256 ----------------
__global__ void addln_kernel(const float* __restrict__ a, const float* __restrict__ b,
                             const float* __restrict__ g, const float* __restrict__ be,
                             float* __restrict__ o) {
    int row = blockIdx.x;
    const float* pa = a + (size_t)row * D_MODEL;
    const float* pb = b ? b + (size_t)row * D_MODEL : nullptr;
    float x[3];
    float s = 0.f, sq = 0.f;
#pragma unroll
    for (int j = 0; j < 3; j++) {
        int i = threadIdx.x + j * 256;
        float v = pa[i];
        if (pb) v += pb[i];
        x[j] = v; s += v; sq += v * v;
    }
    __shared__ float sb[16];
    unsigned wid = threadIdx.x >> 5, lane = threadIdx.x & 31;
#pragma unroll
    for (int off = 16; off; off >>= 1) {
        s  += __shfl_xor_sync(0xffffffffu, s,  off);
        sq += __shfl_xor_sync(0xffffffffu, sq, off);
    }
    if (lane == 0) { sb[wid] = s; sb[8 + wid] = sq; }
    __syncthreads();
    if (threadIdx.x < 32) {
        float s2 = (lane < 8) ? sb[lane] : 0.f;
        float q2 = (lane < 8) ? sb[8 + lane] : 0.f;
#pragma unroll
        for (int off = 4; off; off >>= 1) {
            s2 += __shfl_xor_sync(0xffffffffu, s2, off);
            q2 += __shfl_xor_sync(0xffffffffu, q2, off);
        }
        if (lane == 0) { sb[0] = s2; sb[1] = q2; }
    }
    __syncthreads();
    float mean = sb[0] * (1.f / 768.f);
    float var  = sb[1] * (1.f / 768.f) - mean * mean;
    float rs   = rsqrtf(var + 1e-5f);
    float* po = o + (size_t)row * D_MODEL;
#pragma unroll
    for (int j = 0; j < 3; j++) {
        int i = threadIdx.x + j * 256;
        po[i] = (x[j] - mean) * rs * g[i] + be[i];
    }
}

// ---------------- row softmax ----------------
template <int PER>
__global__ void softmax_kernel(float* __restrict__ S, int len) {
    size_t row = blockIdx.x;
    float* p = S + row * (size_t)len;
    float v[PER];
    float mx = -3.0e38f;
#pragma unroll
    for (int j = 0; j < PER; j++) {
        v[j] = p[threadIdx.x + j * 256];
        mx = fmaxf(mx, v[j]);
    }
    __shared__ float sb[9];
    unsigned wid = threadIdx.x >> 5, lane = threadIdx.x & 31;
#pragma unroll
    for (int off = 16; off; off >>= 1) mx = fmaxf(mx, __shfl_xor_sync(0xffffffffu, mx, off));
    if (lane == 0) sb[wid] = mx;
    __syncthreads();
    if (threadIdx.x < 32) {
        float m = (lane < 8) ? sb[lane] : -3.0e38f;
#pragma unroll
        for (int off = 4; off; off >>= 1) m = fmaxf(m, __shfl_xor_sync(0xffffffffu, m, off));
        if (lane == 0) sb[8] = m;
    }
    __syncthreads();
    mx = sb[8];
    float sum = 0.f;
#pragma unroll
    for (int j = 0; j < PER; j++) { v[j] = expf(v[j] - mx); sum += v[j]; }
    __syncthreads();
#pragma unroll
    for (int off = 16; off; off >>= 1) sum += __shfl_xor_sync(0xffffffffu, sum, off);
    if (lane == 0) sb[wid] = sum;
    __syncthreads();
    if (threadIdx.x < 32) {
        float m = (lane < 8) ? sb[lane] : 0.f;
#pragma unroll
        for (int off = 4; off; off >>= 1) m += __shfl_xor_sync(0xffffffffu, m, off);
        if (lane == 0) sb[8] = m;
    }
    __syncthreads();
    float inv = 1.f / sb[8];
#pragma unroll
    for (int j = 0; j < PER; j++) p[threadIdx.x + j * 256] = v[j] * inv;
}

// ---------------- wmma typedefs ----------------
using FragA  = wmma::fragment<wmma::matrix_a, 16, 16, 8, wmma::precision::tf32, wmma::row_major>;
using FragB  = wmma::fragment<wmma::matrix_b, 16, 16, 8, wmma::precision::tf32, wmma::row_major>;
using FragBT = wmma::fragment<wmma::matrix_b, 16, 16, 8, wmma::precision::tf32, wmma::col_major>;
using FragC  = wmma::fragment<wmma::accumulator, 16, 16, 8, float>;

extern __shared__ float smdyn[];

// ---------------- multi-output GEMM: 128x128x32, cp.async 2-stage ----------------
// blockIdx.z selects weight/bias/resid/output set. Warp tile 32x64 (8 warps, 4x2).
struct Ptrs3 {
    const float* W[3];
    const float* Bi[3];
    const float* R[3];
    float* C[3];
};

#define G_ALD 36
#define G_BLD 132
#define G_ASZ (128 * G_ALD)
#define G_BSZ (32 * G_BLD)
#define G_STG (G_ASZ + G_BSZ)
#define GEMM_SMEM (2 * G_STG * 4)   /* 70656 bytes */

__global__ __launch_bounds__(256) void gemm_bias_kernel(
    const float* __restrict__ A, Ptrs3 P, int M, int N, int K, int relu) {
    const float* W     = P.W[blockIdx.z];
    const float* bias  = P.Bi[blockIdx.z];
    const float* resid = P.R[blockIdx.z];
    float*       C     = P.C[blockIdx.z];

    float* As[2] = {smdyn,          smdyn + G_STG};
    float* Bs[2] = {smdyn + G_ASZ,  smdyn + G_STG + G_ASZ};
    int tid = threadIdx.x;
    int m0 = blockIdx.y * 128, n0 = blockIdx.x * 128;
    int warp = tid >> 5, wm = warp & 3, wn = warp >> 2;

    FragC acc[2][4];
#pragma unroll
    for (int i = 0; i < 2; i++)
#pragma unroll
        for (int j = 0; j < 4; j++) wmma::fill_fragment(acc[i][j], 0.f);

    auto load_tile = [&](int s, int k0) {
#pragma unroll
        for (int i = 0; i < 4; i++) {
            int p = tid + i * 256, r = p >> 3, c = (p & 7) * 4;
            cp16(&As[s][r * G_ALD + c], &A[(size_t)(m0 + r) * K + k0 + c]);
        }
#pragma unroll
        for (int i = 0; i < 4; i++) {
            int p = tid + i * 256, r = p >> 5, c = (p & 31) * 4;
            cp16(&Bs[s][r * G_BLD + c], &W[(size_t)(k0 + r) * N + n0 + c]);
        }
        cp_commit();
    };

    int nk = K / 32;
    load_tile(0, 0);
    for (int kt = 0; kt < nk; kt++) {
        int s = kt & 1;
        if (kt + 1 < nk) {
            load_tile(s ^ 1, (kt + 1) * 32);
            asm volatile("cp.async.wait_group 1;");
        } else {
            asm volatile("cp.async.wait_group 0;");
        }
        __syncthreads();
#pragma unroll
        for (int kk = 0; kk < 32; kk += 8) {
            FragA fa[2]; FragB fb[4];
#pragma unroll
            for (int i = 0; i < 2; i++) {
                wmma::load_matrix_sync(fa[i], &As[s][(wm * 32 + i * 16) * G_ALD + kk], G_ALD);
#pragma unroll
                for (int t = 0; t < fa[i].num_elements; t++) fa[i].x[t] = wmma::__float_to_tf32(fa[i].x[t]);
            }
#pragma unroll
            for (int j = 0; j < 4; j++) {
                wmma::load_matrix_sync(fb[j], &Bs[s][kk * G_BLD + wn * 64 + j * 16], G_BLD);
#pragma unroll
                for (int t = 0; t < fb[j].num_elements; t++) fb[j].x[t] = wmma::__float_to_tf32(fb[j].x[t]);
            }
#pragma unroll
            for (int i = 0; i < 2; i++)
#pragma unroll
                for (int j = 0; j < 4; j++) wmma::mma_sync(acc[i][j], fa[i], fb[j], acc[i][j]);
        }
        __syncthreads();
    }
    // epilogue (staged through smem)
    float* Cs = smdyn;
#pragma unroll
    for (int i = 0; i < 2; i++)
#pragma unroll
        for (int j = 0; j < 4; j++)
            wmma::store_matrix_sync(&Cs[(wm * 32 + i * 16) * G_BLD + wn * 64 + j * 16],
                                    acc[i][j], G_BLD, wmma::mem_row_major);
    __syncthreads();
#pragma unroll
    for (int i = 0; i < 16; i++) {
        int p = tid + i * 256, r = p >> 5, c = (p & 31) * 4;
        float4 v = *(float4*)&Cs[r * G_BLD + c];
        int gc = n0 + c;
        float4 bv = *(const float4*)&bias[gc];
        v.x += bv.x; v.y += bv.y; v.z += bv.z; v.w += bv.w;
        size_t off = (size_t)(m0 + r) * N + gc;
        if (resid) {
            float4 rv = *(const float4*)&resid[off];
            v.x += rv.x; v.y += rv.y; v.z += rv.z; v.w += rv.w;
        }
        if (relu) {
            v.x = fmaxf(v.x, 0.f); v.y = fmaxf(v.y, 0.f);
            v.z = fmaxf(v.z, 0.f); v.w = fmaxf(v.w, 0.f);
        }
        *(float4*)&C[off] = v;
    }
}

// ---------------- batched strided GEMM (attention), cp.async 2-stage ----------------
// BM=128, BK=32. BT: C = A @ B^T (scores). !BT: C = A @ B (probs @ V).
template <int BN, bool BT>
__global__ __launch_bounds__(256) void bgemm_kernel(
    const float* __restrict__ A, int lda, long sAb, long sAh,
    const float* __restrict__ Bm, int ldb, long sBb, long sBh,
    float* __restrict__ C, int ldc, long sCb, long sCh,
    int M, int N, int K, float alpha) {
    constexpr int ALD = 36;
    constexpr int BROWS = BT ? BN : 32;
    constexpr int BLD = BT ? 36 : (BN + 4);
    constexpr int ASZ = 128 * ALD;
    constexpr int BSZ = BROWS * BLD;
    constexpr int STG = ASZ + BSZ;
    constexpr int WN = BN / 2;
    constexpr int NF = WN / 16;

    int z = blockIdx.z, bi = z / HEADS, hi = z % HEADS;
    const float* Ab = A  + (size_t)bi * sAb + (size_t)hi * sAh;
    const float* Bb = Bm + (size_t)bi * sBb + (size_t)hi * sBh;
    float*       Cb = C  + (size_t)bi * sCb + (size_t)hi * sCh;

    float* As[2] = {smdyn,         smdyn + STG};
    float* Bs[2] = {smdyn + ASZ,   smdyn + STG + ASZ};
    int tid = threadIdx.x;
    int m0 = blockIdx.y * 128, n0 = blockIdx.x * BN;
    int warp = tid >> 5, wm = warp & 3, wn = warp >> 2;

    FragC acc[2][NF];
#pragma unroll
    for (int i = 0; i < 2; i++)
#pragma unroll
        for (int j = 0; j < NF; j++) wmma::fill_fragment(acc[i][j], 0.f);

    auto load_tile = [&](int s, int k0) {
#pragma unroll
        for (int i = 0; i < 4; i++) {
            int p = tid + i * 256, r = p >> 3, c = (p & 7) * 4;
            cp16(&As[s][r * ALD + c], &Ab[(size_t)(m0 + r) * lda + k0 + c]);
        }
        if (BT) {
            constexpr int IT = BN * 8 / 256;
#pragma unroll
            for (int i = 0; i < IT; i++) {
                int p = tid + i * 256, r = p >> 3, c = (p & 7) * 4;
                cp16(&Bs[s][r * BLD + c], &Bb[(size_t)(n0 + r) * ldb + k0 + c]);
            }
        } else {
            constexpr int RF4 = BN / 4;            // float4 per row
            constexpr int IT = 32 * RF4 / 256;
#pragma unroll
            for (int i = 0; i < IT; i++) {
                int p = tid + i * 256, r = p / RF4, c = (p % RF4) * 4;
                cp16(&Bs[s][r * BLD + c], &Bb[(size_t)(k0 + r) * ldb + n0 + c]);
            }
        }
        cp_commit();
    };

    int nk = K / 32;
    load_tile(0, 0);
    for (int kt = 0; kt < nk; kt++) {
        int s = kt & 1;
        if (kt + 1 < nk) {
            load_tile(s ^ 1, (kt + 1) * 32);
            asm volatile("cp.async.wait_group 1;");
        } else {
            asm volatile("cp.async.wait_group 0;");
        }
        __syncthreads();
#pragma unroll
        for (int kk = 0; kk < 32; kk += 8) {
            FragA fa[2];
#pragma unroll
            for (int i = 0; i < 2; i++) {
                wmma::load_matrix_sync(fa[i], &As[s][(wm * 32 + i * 16) * ALD + kk], ALD);
#pragma unroll
                for (int t = 0; t < fa[i].num_elements; t++) fa[i].x[t] = wmma::__float_to_tf32(fa[i].x[t]);
            }
            if (BT) {
                FragBT fb[NF];
#pragma unroll
                for (int j = 0; j < NF; j++) {
                    wmma::load_matrix_sync(fb[j], &Bs[s][(wn * WN + j * 16) * BLD + kk], BLD);
#pragma unroll
                    for (int t = 0; t < fb[j].num_elements; t++) fb[j].x[t] = wmma::__float_to_tf32(fb[j].x[t]);
                }
#pragma unroll
                for (int i = 0; i < 2; i++)
#pragma unroll
                    for (int j = 0; j < NF; j++) wmma::mma_sync(acc[i][j], fa[i], fb[j], acc[i][j]);
            } else {
                FragB fb[NF];
#pragma unroll
                for (int j = 0; j < NF; j++) {
                    wmma::load_matrix_sync(fb[j], &Bs[s][kk * BLD + wn * WN + j * 16], BLD);
#pragma unroll
                    for (int t = 0; t < fb[j].num_elements; t++) fb[j].x[t] = wmma::__float_to_tf32(fb[j].x[t]);
                }
#pragma unroll
                for (int i = 0; i < 2; i++)
#pragma unroll
                    for (int j = 0; j < NF; j++) wmma::mma_sync(acc[i][j], fa[i], fb[j], acc[i][j]);
            }
        }
        __syncthreads();
    }
    constexpr int CLDL = BN + 4;
    float* Cs = smdyn;
#pragma unroll
    for (int i = 0; i < 2; i++)
#pragma unroll
        for (int j = 0; j < NF; j++)
            wmma::store_matrix_sync(&Cs[(wm * 32 + i * 16) * CLDL + wn * WN + j * 16],
                                    acc[i][j], CLDL, wmma::mem_row_major);
    __syncthreads();
    constexpr int RF4 = BN / 4;
    constexpr int IT = 128 * RF4 / 256;
#pragma unroll
    for (int i = 0; i < IT; i++) {
        int p = tid + i * 256, r = p / RF4, c = (p % RF4) * 4;
        float4 v = *(float4*)&Cs[r * CLDL + c];
        v.x *= alpha; v.y *= alpha; v.z *= alpha; v.w *= alpha;
        *(float4*)&Cb[(size_t)(m0 + r) * ldc + n0 + c] = v;
    }
}

#define BG_SMEM_SC ((128*36 + 128*36) * 2 * 4)   /* 73728: scores BN=128 BT */
#define BG_SMEM_PV ((128*36 + 32*68)  * 2 * 4)   /* 54272: PV BN=64 */

// ---------------- launcher ----------------
extern "C" void kernel_launch(void* const* d_in, const int* in_sizes, int n_in,
                              void* d_out, int out_size) {
    (void)in_sizes; (void)n_in; (void)out_size;
    const float* image  = (const float*)d_in[0];
    const float* prompt = (const float*)d_in[1];
    const float* posi   = (const float*)d_in[2];
    const float* posp   = (const float*)d_in[3];
    const float* ln1g = (const float*)d_in[4],  *ln1b = (const float*)d_in[5];
    const float* ln2g = (const float*)d_in[6],  *ln2b = (const float*)d_in[7];
    const float* ln3g = (const float*)d_in[8],  *ln3b = (const float*)d_in[9];
    const float* lnig = (const float*)d_in[10], *lnib = (const float*)d_in[11];
    const float* pp_wq = (const float*)d_in[12], *pp_bq = (const float*)d_in[13];
    const float* pp_wk = (const float*)d_in[14], *pp_bk = (const float*)d_in[15];
    const float* pp_wv = (const float*)d_in[16], *pp_bv = (const float*)d_in[17];
    const float* pp_wo = (const float*)d_in[18], *pp_bo = (const float*)d_in[19];
    const float* pi_wq = (const float*)d_in[20], *pi_bq = (const float*)d_in[21];
    const float* pi_wk = (const float*)d_in[22], *pi_bk = (const float*)d_in[23];
    const float* pi_wv = (const float*)d_in[24], *pi_bv = (const float*)d_in[25];
    const float* pi_wo = (const float*)d_in[26], *pi_bo = (const float*)d_in[27];
    const float* ff_w1 = (const float*)d_in[28], *ff_b1 = (const float*)d_in[29];
    const float* ff_w2 = (const float*)d_in[30], *ff_b2 = (const float*)d_in[31];
    float* out = (float*)d_out;

    float *prompt0, *x, *xi, *q, *k, *v, *sc, *attn, *p1, *p2, *hbuf;
    cudaGetSymbolAddress((void**)&prompt0, g_prompt0);
    cudaGetSymbolAddress((void**)&x,       g_x);
    cudaGetSymbolAddress((void**)&xi,      g_xi);
    cudaGetSymbolAddress((void**)&q,       g_q);
    cudaGetSymbolAddress((void**)&k,       g_k);
    cudaGetSymbolAddress((void**)&v,       g_v);
    cudaGetSymbolAddress((void**)&sc,      g_scores);
    cudaGetSymbolAddress((void**)&attn,    g_attn);
    cudaGetSymbolAddress((void**)&p1,      g_p1);
    cudaGetSymbolAddress((void**)&p2,      g_p2);
    cudaGetSymbolAddress((void**)&hbuf,    g_h);

    cudaFuncSetAttribute(gemm_bias_kernel, cudaFuncAttributeMaxDynamicSharedMemorySize, GEMM_SMEM);
    cudaFuncSetAttribute(bgemm_kernel<128, true>,  cudaFuncAttributeMaxDynamicSharedMemorySize, BG_SMEM_SC);
    cudaFuncSetAttribute(bgemm_kernel<64, false>,  cudaFuncAttributeMaxDynamicSharedMemorySize, BG_SMEM_PV);

    const dim3 gp(D_MODEL / 128, TOKP / 128);   // (6, 32)

    // 1. prompt0 = prompt + posp
    add4_kernel<<<(TOKP * D_MODEL / 4 + 255) / 256, 256>>>(
        (const float4*)prompt, (const float4*)posp, (float4*)prompt0, TOKP * D_MODEL / 4);
    // 2. x = LN(prompt0)
    addln_kernel<<<TOKP, 256>>>(prompt0, nullptr, ln1g, ln1b, x);
    // 3. self-attn QKV fused (z = 3)
    {
        Ptrs3 P = {{pp_wq, pp_wk, pp_wv}, {pp_bq, pp_bk, pp_bv},
                   {nullptr, nullptr, nullptr}, {q, k, v}};
        gemm_bias_kernel<<<dim3(6, 32, 3), 256, GEMM_SMEM>>>(x, P, TOKP, D_MODEL, D_MODEL, 0);
    }
    // 4. scores = Q @ K^T / 8
    bgemm_kernel<128, true><<<dim3(SP / 128, SP / 128, NB * HEADS), 256, BG_SMEM_SC>>>(
        q, D_MODEL, (long)SP * D_MODEL, D_HEAD,
        k, D_MODEL, (long)SP * D_MODEL, D_HEAD,
        sc, SP, (long)HEADS * SP * SP, (long)SP * SP,
        SP, SP, D_HEAD, 0.125f);
    // 5. softmax (len 256)
    softmax_kernel<1><<<NB * HEADS * SP, 256>>>(sc, SP);
    // 6. attn = P @ V
    bgemm_kernel<64, false><<<dim3(1, SP / 128, NB * HEADS), 256, BG_SMEM_PV>>>(
        sc, SP, (long)HEADS * SP * SP, (long)SP * SP,
        v, D_MODEL, (long)SP * D_MODEL, D_HEAD,
        attn, D_MODEL, (long)SP * D_MODEL, D_HEAD,
        SP, D_HEAD, SP, 1.f);
    // 7. p1 = attn @ Wo + bo + prompt
    {
        Ptrs3 P = {{pp_wo, nullptr, nullptr}, {pp_bo, nullptr, nullptr},
                   {prompt, nullptr, nullptr}, {p1, nullptr, nullptr}};
        gemm_bias_kernel<<<dim3(6, 32, 1), 256, GEMM_SMEM>>>(attn, P, TOKP, D_MODEL, D_MODEL, 0);
    }
    // 8. x = LN(p1 + prompt0)
    addln_kernel<<<TOKP, 256>>>(p1, prompt0, ln2g, ln2b, x);
    // 9. xi = LN(image + posi)
    addln_kernel<<<TOKI, 256>>>(image, posi, lnig, lnib, xi);
    // 10. cross Q projection
    {
        Ptrs3 P = {{pi_wq, nullptr, nullptr}, {pi_bq, nullptr, nullptr},
                   {nullptr, nullptr, nullptr}, {q, nullptr, nullptr}};
        gemm_bias_kernel<<<dim3(6, 32, 1), 256, GEMM_SMEM>>>(x, P, TOKP, D_MODEL, D_MODEL, 0);
    }
    // 11. image K,V fused (z = 2)
    {
        Ptrs3 P = {{pi_wk, pi_wv, nullptr}, {pi_bk, pi_bv, nullptr},
                   {nullptr, nullptr, nullptr}, {k, v, nullptr}};
        gemm_bias_kernel<<<dim3(6, 128, 2), 256, GEMM_SMEM>>>(xi, P, TOKI, D_MODEL, D_MODEL, 0);
    }
    // 12. cross scores = Q @ K^T / 8
    bgemm_kernel<128, true><<<dim3(SI / 128, SP / 128, NB * HEADS), 256, BG_SMEM_SC>>>(
        q, D_MODEL, (long)SP * D_MODEL, D_HEAD,
        k, D_MODEL, (long)SI * D_MODEL, D_HEAD,
        sc, SI, (long)HEADS * SP * SI, (long)SP * SI,
        SP, SI, D_HEAD, 0.125f);
    // 13. softmax (len 1024)
    softmax_kernel<4><<<NB * HEADS * SP, 256>>>(sc, SI);
    // 14. attn = P @ V
    bgemm_kernel<64, false><<<dim3(1, SP / 128, NB * HEADS), 256, BG_SMEM_PV>>>(
        sc, SI, (long)HEADS * SP * SI, (long)SP * SI,
        v, D_MODEL, (long)SI * D_MODEL, D_HEAD,
        attn, D_MODEL, (long)SP * D_MODEL, D_HEAD,
        SP, D_HEAD, SI, 1.f);
    // 15. p2 = attn @ Wo + bo + p1
    {
        Ptrs3 P = {{pi_wo, nullptr, nullptr}, {pi_bo, nullptr, nullptr},
                   {p1, nullptr, nullptr}, {p2, nullptr, nullptr}};
        gemm_bias_kernel<<<dim3(6, 32, 1), 256, GEMM_SMEM>>>(attn, P, TOKP, D_MODEL, D_MODEL, 0);
    }
    // 16. x = LN(p2 + prompt0)
    addln_kernel<<<TOKP, 256>>>(p2, prompt0, ln3g, ln3b, x);
    // 17. h = relu(x @ W1 + b1)
    {
        Ptrs3 P = {{ff_w1, nullptr, nullptr}, {ff_b1, nullptr, nullptr},
                   {nullptr, nullptr, nullptr}, {hbuf, nullptr, nullptr}};
        gemm_bias_kernel<<<dim3(6, 32, 1), 256, GEMM_SMEM>>>(x, P, TOKP, D_MODEL, D_MODEL, 1);
    }
    // 18. out = h @ W2 + b2
    {
        Ptrs3 P = {{ff_w2, nullptr, nullptr}, {ff_b2, nullptr, nullptr},
                   {nullptr, nullptr, nullptr}, {out, nullptr, nullptr}};
        gemm_bias_kernel<<<dim3(6, 32, 1), 256, GEMM_SMEM>>>(hbuf, P, TOKP, D_MODEL, D_MODEL, 0);
    }
}

// round 3
// speedup vs baseline: 1.1261x; 1.1261x over previous
#include <cuda_runtime.h>
#include <mma.h>
#include <cstdint>

using namespace nvcuda;

#define D_MODEL 768
#define HEADS   12
#define D_HEAD  64
#define NB      16
#define SP      256
#define SI      1024
#define TOKP    (NB*SP)     /* 4096  */
#define TOKI    (NB*SI)     /* 16384 */

// ---------------- scratch (device globals: no allocations allowed) ----------------
__device__ float g_prompt0[TOKP*D_MODEL];
__device__ float g_x      [TOKP*D_MODEL];
__device__ float g_xi     [TOKI*D_MODEL];
__device__ float g_q      [TOKP*D_MODEL];
__device__ float g_k      [TOKI*D_MODEL];
__device__ float g_v      [TOKI*D_MODEL];
__device__ float g_scores [(size_t)NB*HEADS*SP*SI];
__device__ float g_attn   [TOKP*D_MODEL];
__device__ float g_p1     [TOKP*D_MODEL];
__device__ float g_p2     [TOKP*D_MODEL];
__device__ float g_h      [TOKP*D_MODEL];

// ---------------- cp.async helpers ----------------
__device__ __forceinline__ void cp16(float* s, const float* g) {
    uint32_t sa = (uint32_t)__cvta_generic_to_shared(s);
    asm volatile("cp.async.cg.shared.global [%0], [%1], 16;" :: "r"(sa), "l"(g));
}
__device__ __forceinline__ void cp_commit() { asm volatile("cp.async.commit_group;"); }

// ---------------- elementwise add (float4) ----------------
__global__ void add4_kernel(const float4* __restrict__ a, const float4* __restrict__ b,
                            float4* __restrict__ o, int n4) {
    int i = blockIdx.x * blockDim.x + threadIdx.x;
    if (i < n4) {
        float4 x = a[i], y = b[i];
        x.x += y.x; x.y += y.y; x.z += y.z; x.w += y.w;
        o[i] = x;
    }
}

// ---------------- (optional add) + layernorm ----------------
__global__ void addln_kernel(const float* __restrict__ a, const float* __restrict__ b,
                             const float* __restrict__ g, const float* __restrict__ be,
                             float* __restrict__ o) {
    int row = blockIdx.x;
    const float* pa = a + (size_t)row * D_MODEL;
    const float* pb = b ? b + (size_t)row * D_MODEL : nullptr;
    float x[3];
    float s = 0.f, sq = 0.f;
#pragma unroll
    for (int j = 0; j < 3; j++) {
        int i = threadIdx.x + j * 256;
        float v = pa[i];
        if (pb) v += pb[i];
        x[j] = v; s += v; sq += v * v;
    }
    __shared__ float sb[16];
    unsigned wid = threadIdx.x >> 5, lane = threadIdx.x & 31;
#pragma unroll
    for (int off = 16; off; off >>= 1) {
        s  += __shfl_xor_sync(0xffffffffu, s,  off);
        sq += __shfl_xor_sync(0xffffffffu, sq, off);
    }
    if (lane == 0) { sb[wid] = s; sb[8 + wid] = sq; }
    __syncthreads();
    if (threadIdx.x < 32) {
        float s2 = (lane < 8) ? sb[lane] : 0.f;
        float q2 = (lane < 8) ? sb[8 + lane] : 0.f;
#pragma unroll
        for (int off = 4; off; off >>= 1) {
            s2 += __shfl_xor_sync(0xffffffffu, s2, off);
            q2 += __shfl_xor_sync(0xffffffffu, q2, off);
        }
        if (lane == 0) { sb[0] = s2; sb[1] = q2; }
    }
    __syncthreads();
    float mean = sb[0] * (1.f / 768.f);
    float var  = sb[1] * (1.f / 768.f) - mean * mean;
    float rs   = rsqrtf(var + 1e-5f);
    float* po = o + (size_t)row * D_MODEL;
#pragma unroll
    for (int j = 0; j < 3; j++) {
        int i = threadIdx.x + j * 256;
        po[i] = (x[j] - mean) * rs * g[i] + be[i];
    }
}

// ---------------- row softmax ----------------
template <int PER>
__global__ void softmax_kernel(float* __restrict__ S, int len) {
    size_t row = blockIdx.x;
    float* p = S + row * (size_t)len;
    float v[PER];
    float mx = -3.0e38f;
#pragma unroll
    for (int j = 0; j < PER; j++) {
        v[j] = p[threadIdx.x + j * 256];
        mx = fmaxf(mx, v[j]);
    }
    __shared__ float sb[9];
    unsigned wid = threadIdx.x >> 5, lane = threadIdx.x & 31;
#pragma unroll
    for (int off = 16; off; off >>= 1) mx = fmaxf(mx, __shfl_xor_sync(0xffffffffu, mx, off));
    if (lane == 0) sb[wid] = mx;
    __syncthreads();
    if (threadIdx.x < 32) {
        float m = (lane < 8) ? sb[lane] : -3.0e38f;
#pragma unroll
        for (int off = 4; off; off >>= 1) m = fmaxf(m, __shfl_xor_sync(0xffffffffu, m, off));
        if (lane == 0) sb[8] = m;
    }
    __syncthreads();
    mx = sb[8];
    float sum = 0.f;
#pragma unroll
    for (int j = 0; j < PER; j++) { v[j] = expf(v[j] - mx); sum += v[j]; }
    __syncthreads();
#pragma unroll
    for (int off = 16; off; off >>= 1) sum += __shfl_xor_sync(0xffffffffu, sum, off);
    if (lane == 0) sb[wid] = sum;
    __syncthreads();
    if (threadIdx.x < 32) {
        float m = (lane < 8) ? sb[lane] : 0.f;
#pragma unroll
        for (int off = 4; off; off >>= 1) m += __shfl_xor_sync(0xffffffffu, m, off);
        if (lane == 0) sb[8] = m;
    }
    __syncthreads();
    float inv = 1.f / sb[8];
#pragma unroll
    for (int j = 0; j < PER; j++) p[threadIdx.x + j * 256] = v[j] * inv;
}

// ---------------- wmma typedefs ----------------
using FragA  = wmma::fragment<wmma::matrix_a, 16, 16, 8, wmma::precision::tf32, wmma::row_major>;
using FragB  = wmma::fragment<wmma::matrix_b, 16, 16, 8, wmma::precision::tf32, wmma::row_major>;
using FragBT = wmma::fragment<wmma::matrix_b, 16, 16, 8, wmma::precision::tf32, wmma::col_major>;
using FragC  = wmma::fragment<wmma::accumulator, 16, 16, 8, float>;

extern __shared__ float smdyn[];

// ================= dense GEMM: 128x64x32, cp.async 2-stage, warp 32x32 ===========
// blockIdx.z selects weight/bias/resid/output set (multi-output fusion).
struct Ptrs3 {
    const float* W[3];
    const float* Bi[3];
    const float* R[3];
    float* C[3];
};

#define G_ALD 36
#define G_BLD 68
#define G_ASZ (128 * G_ALD)      /* 4608 */
#define G_BSZ (32 * G_BLD)       /* 2176 */
#define G_STG (G_ASZ + G_BSZ)    /* 6784 */
#define GEMM_SMEM (2 * G_STG * 4)   /* 54272 bytes */

__global__ __launch_bounds__(256, 2) void gemm_bias_kernel(
    const float* __restrict__ A, Ptrs3 P, int M, int N, int K, int relu) {
    const float* W     = P.W[blockIdx.z];
    const float* bias  = P.Bi[blockIdx.z];
    const float* resid = P.R[blockIdx.z];
    float*       C     = P.C[blockIdx.z];

    float* As[2] = {smdyn,          smdyn + G_STG};
    float* Bs[2] = {smdyn + G_ASZ,  smdyn + G_STG + G_ASZ};
    int tid = threadIdx.x;
    int m0 = blockIdx.y * 128, n0 = blockIdx.x * 64;
    int warp = tid >> 5, wm = warp & 3, wn = warp >> 2;

    FragC acc[2][2];
#pragma unroll
    for (int i = 0; i < 2; i++)
#pragma unroll
        for (int j = 0; j < 2; j++) wmma::fill_fragment(acc[i][j], 0.f);

    auto load_tile = [&](int s, int k0) {
#pragma unroll
        for (int i = 0; i < 4; i++) {
            int p = tid + i * 256, r = p >> 3, c = (p & 7) * 4;
            cp16(&As[s][r * G_ALD + c], &A[(size_t)(m0 + r) * K + k0 + c]);
        }
#pragma unroll
        for (int i = 0; i < 2; i++) {
            int p = tid + i * 256, r = p >> 4, c = (p & 15) * 4;
            cp16(&Bs[s][r * G_BLD + c], &W[(size_t)(k0 + r) * N + n0 + c]);
        }
        cp_commit();
    };

    int nk = K / 32;
    load_tile(0, 0);
    for (int kt = 0; kt < nk; kt++) {
        int s = kt & 1;
        if (kt + 1 < nk) {
            load_tile(s ^ 1, (kt + 1) * 32);
            asm volatile("cp.async.wait_group 1;");
        } else {
            asm volatile("cp.async.wait_group 0;");
        }
        __syncthreads();
#pragma unroll
        for (int kk = 0; kk < 32; kk += 8) {
            FragA fa[2]; FragB fb[2];
#pragma unroll
            for (int i = 0; i < 2; i++) {
                wmma::load_matrix_sync(fa[i], &As[s][(wm * 32 + i * 16) * G_ALD + kk], G_ALD);
#pragma unroll
                for (int t = 0; t < fa[i].num_elements; t++) fa[i].x[t] = wmma::__float_to_tf32(fa[i].x[t]);
            }
#pragma unroll
            for (int j = 0; j < 2; j++) {
                wmma::load_matrix_sync(fb[j], &Bs[s][kk * G_BLD + wn * 32 + j * 16], G_BLD);
#pragma unroll
                for (int t = 0; t < fb[j].num_elements; t++) fb[j].x[t] = wmma::__float_to_tf32(fb[j].x[t]);
            }
#pragma unroll
            for (int i = 0; i < 2; i++)
#pragma unroll
                for (int j = 0; j < 2; j++) wmma::mma_sync(acc[i][j], fa[i], fb[j], acc[i][j]);
        }
        __syncthreads();
    }
    // epilogue staged through smem
    float* Cs = smdyn;
#pragma unroll
    for (int i = 0; i < 2; i++)
#pragma unroll
        for (int j = 0; j < 2; j++)
            wmma::store_matrix_sync(&Cs[(wm * 32 + i * 16) * G_BLD + wn * 32 + j * 16],
                                    acc[i][j], G_BLD, wmma::mem_row_major);
    __syncthreads();
#pragma unroll
    for (int i = 0; i < 8; i++) {
        int p = tid + i * 256, r = p >> 4, c = (p & 15) * 4;
        float4 v = *(float4*)&Cs[r * G_BLD + c];
        int gc = n0 + c;
        float4 bv = *(const float4*)&bias[gc];
        v.x += bv.x; v.y += bv.y; v.z += bv.z; v.w += bv.w;
        size_t off = (size_t)(m0 + r) * N + gc;
        if (resid) {
            float4 rv = *(const float4*)&resid[off];
            v.x += rv.x; v.y += rv.y; v.z += rv.z; v.w += rv.w;
        }
        if (relu) {
            v.x = fmaxf(v.x, 0.f); v.y = fmaxf(v.y, 0.f);
            v.z = fmaxf(v.z, 0.f); v.w = fmaxf(v.w, 0.f);
        }
        *(float4*)&C[off] = v;
    }
}

// ============ batched strided GEMM (attention): 128x64x32, 2-stage, warp 32x32 =====
// BT: C = A @ B^T (scores).  !BT: C = A @ B (probs @ V).
template <bool BT>
__global__ __launch_bounds__(256, 2) void bgemm_kernel(
    const float* __restrict__ A, int lda, long sAb, long sAh,
    const float* __restrict__ Bm, int ldb, long sBb, long sBh,
    float* __restrict__ C, int ldc, long sCb, long sCh,
    int M, int N, int K, float alpha) {
    constexpr int ALD = 36;
    constexpr int BROWS = BT ? 64 : 32;
    constexpr int BLD = BT ? 36 : 68;
    constexpr int ASZ = 128 * ALD;
    constexpr int BSZ = BROWS * BLD;
    constexpr int STG = ASZ + BSZ;

    int z = blockIdx.z, bi = z / HEADS, hi = z % HEADS;
    const float* Ab = A  + (size_t)bi * sAb + (size_t)hi * sAh;
    const float* Bb = Bm + (size_t)bi * sBb + (size_t)hi * sBh;
    float*       Cb = C  + (size_t)bi * sCb + (size_t)hi * sCh;

    float* As[2] = {smdyn,         smdyn + STG};
    float* Bs[2] = {smdyn + ASZ,   smdyn + STG + ASZ};
    int tid = threadIdx.x;
    int m0 = blockIdx.y * 128, n0 = blockIdx.x * 64;
    int warp = tid >> 5, wm = warp & 3, wn = warp >> 2;

    FragC acc[2][2];
#pragma unroll
    for (int i = 0; i < 2; i++)
#pragma unroll
        for (int j = 0; j < 2; j++) wmma::fill_fragment(acc[i][j], 0.f);

    auto load_tile = [&](int s, int k0) {
#pragma unroll
        for (int i = 0; i < 4; i++) {
            int p = tid + i * 256, r = p >> 3, c = (p & 7) * 4;
            cp16(&As[s][r * ALD + c], &Ab[(size_t)(m0 + r) * lda + k0 + c]);
        }
        if (BT) {
#pragma unroll
            for (int i = 0; i < 2; i++) {
                int p = tid + i * 256, r = p >> 3, c = (p & 7) * 4;   // 64 rows x 32
                cp16(&Bs[s][r * BLD + c], &Bb[(size_t)(n0 + r) * ldb + k0 + c]);
            }
        } else {
#pragma unroll
            for (int i = 0; i < 2; i++) {
                int p = tid + i * 256, r = p >> 4, c = (p & 15) * 4;  // 32 rows x 64
                cp16(&Bs[s][r * BLD + c], &Bb[(size_t)(k0 + r) * ldb + n0 + c]);
            }
        }
        cp_commit();
    };

    int nk = K / 32;
    load_tile(0, 0);
    for (int kt = 0; kt < nk; kt++) {
        int s = kt & 1;
        if (kt + 1 < nk) {
            load_tile(s ^ 1, (kt + 1) * 32);
            asm volatile("cp.async.wait_group 1;");
        } else {
            asm volatile("cp.async.wait_group 0;");
        }
        __syncthreads();
#pragma unroll
        for (int kk = 0; kk < 32; kk += 8) {
            FragA fa[2];
#pragma unroll
            for (int i = 0; i < 2; i++) {
                wmma::load_matrix_sync(fa[i], &As[s][(wm * 32 + i * 16) * ALD + kk], ALD);
#pragma unroll
                for (int t = 0; t < fa[i].num_elements; t++) fa[i].x[t] = wmma::__float_to_tf32(fa[i].x[t]);
            }
            if (BT) {
                FragBT fb[2];
#pragma unroll
                for (int j = 0; j < 2; j++) {
                    wmma::load_matrix_sync(fb[j], &Bs[s][(wn * 32 + j * 16) * BLD + kk], BLD);
#pragma unroll
                    for (int t = 0; t < fb[j].num_elements; t++) fb[j].x[t] = wmma::__float_to_tf32(fb[j].x[t]);
                }
#pragma unroll
                for (int i = 0; i < 2; i++)
#pragma unroll
                    for (int j = 0; j < 2; j++) wmma::mma_sync(acc[i][j], fa[i], fb[j], acc[i][j]);
            } else {
                FragB fb[2];
#pragma unroll
                for (int j = 0; j < 2; j++) {
                    wmma::load_matrix_sync(fb[j], &Bs[s][kk * BLD + wn * 32 + j * 16], BLD);
#pragma unroll
                    for (int t = 0; t < fb[j].num_elements; t++) fb[j].x[t] = wmma::__float_to_tf32(fb[j].x[t]);
                }
#pragma unroll
                for (int i = 0; i < 2; i++)
#pragma unroll
                    for (int j = 0; j < 2; j++) wmma::mma_sync(acc[i][j], fa[i], fb[j], acc[i][j]);
            }
        }
        __syncthreads();
    }
    constexpr int CLDL = 68;
    float* Cs = smdyn;
#pragma unroll
    for (int i = 0; i < 2; i++)
#pragma unroll
        for (int j = 0; j < 2; j++)
            wmma::store_matrix_sync(&Cs[(wm * 32 + i * 16) * CLDL + wn * 32 + j * 16],
                                    acc[i][j], CLDL, wmma::mem_row_major);
    __syncthreads();
#pragma unroll
    for (int i = 0; i < 8; i++) {
        int p = tid + i * 256, r = p >> 4, c = (p & 15) * 4;
        float4 v = *(float4*)&Cs[r * CLDL + c];
        v.x *= alpha; v.y *= alpha; v.z *= alpha; v.w *= alpha;
        *(float4*)&Cb[(size_t)(m0 + r) * ldc + n0 + c] = v;
    }
}

#define BG_SMEM_SC ((128*36 + 64*36) * 2 * 4)   /* 55296 */
#define BG_SMEM_PV ((128*36 + 32*68) * 2 * 4)   /* 54272 */

// ---------------- launcher ----------------
extern "C" void kernel_launch(void* const* d_in, const int* in_sizes, int n_in,
                              void* d_out, int out_size) {
    (void)in_sizes; (void)n_in; (void)out_size;
    const float* image  = (const float*)d_in[0];
    const float* prompt = (const float*)d_in[1];
    const float* posi   = (const float*)d_in[2];
    const float* posp   = (const float*)d_in[3];
    const float* ln1g = (const float*)d_in[4],  *ln1b = (const float*)d_in[5];
    const float* ln2g = (const float*)d_in[6],  *ln2b = (const float*)d_in[7];
    const float* ln3g = (const float*)d_in[8],  *ln3b = (const float*)d_in[9];
    const float* lnig = (const float*)d_in[10], *lnib = (const float*)d_in[11];
    const float* pp_wq = (const float*)d_in[12], *pp_bq = (const float*)d_in[13];
    const float* pp_wk = (const float*)d_in[14], *pp_bk = (const float*)d_in[15];
    const float* pp_wv = (const float*)d_in[16], *pp_bv = (const float*)d_in[17];
    const float* pp_wo = (const float*)d_in[18], *pp_bo = (const float*)d_in[19];
    const float* pi_wq = (const float*)d_in[20], *pi_bq = (const float*)d_in[21];
    const float* pi_wk = (const float*)d_in[22], *pi_bk = (const float*)d_in[23];
    const float* pi_wv = (const float*)d_in[24], *pi_bv = (const float*)d_in[25];
    const float* pi_wo = (const float*)d_in[26], *pi_bo = (const float*)d_in[27];
    const float* ff_w1 = (const float*)d_in[28], *ff_b1 = (const float*)d_in[29];
    const float* ff_w2 = (const float*)d_in[30], *ff_b2 = (const float*)d_in[31];
    float* out = (float*)d_out;

    float *prompt0, *x, *xi, *q, *k, *v, *sc, *attn, *p1, *p2, *hbuf;
    cudaGetSymbolAddress((void**)&prompt0, g_prompt0);
    cudaGetSymbolAddress((void**)&x,       g_x);
    cudaGetSymbolAddress((void**)&xi,      g_xi);
    cudaGetSymbolAddress((void**)&q,       g_q);
    cudaGetSymbolAddress((void**)&k,       g_k);
    cudaGetSymbolAddress((void**)&v,       g_v);
    cudaGetSymbolAddress((void**)&sc,      g_scores);
    cudaGetSymbolAddress((void**)&attn,    g_attn);
    cudaGetSymbolAddress((void**)&p1,      g_p1);
    cudaGetSymbolAddress((void**)&p2,      g_p2);
    cudaGetSymbolAddress((void**)&hbuf,    g_h);

    cudaFuncSetAttribute(gemm_bias_kernel, cudaFuncAttributeMaxDynamicSharedMemorySize, GEMM_SMEM);
    cudaFuncSetAttribute(bgemm_kernel<true>,  cudaFuncAttributeMaxDynamicSharedMemorySize, BG_SMEM_SC);
    cudaFuncSetAttribute(bgemm_kernel<false>, cudaFuncAttributeMaxDynamicSharedMemorySize, BG_SMEM_PV);

    const dim3 gp(D_MODEL / 64, TOKP / 128);    // (12, 32)
    const dim3 gi(D_MODEL / 64, TOKI / 128);    // (12, 128)

    // 1. prompt0 = prompt + posp
    add4_kernel<<<(TOKP * D_MODEL / 4 + 255) / 256, 256>>>(
        (const float4*)prompt, (const float4*)posp, (float4*)prompt0, TOKP * D_MODEL / 4);
    // 2. x = LN(prompt0)
    addln_kernel<<<TOKP, 256>>>(prompt0, nullptr, ln1g, ln1b, x);
    // 3. self-attn QKV fused (z = 3)
    {
        Ptrs3 P = {{pp_wq, pp_wk, pp_wv}, {pp_bq, pp_bk, pp_bv},
                   {nullptr, nullptr, nullptr}, {q, k, v}};
        gemm_bias_kernel<<<dim3(12, 32, 3), 256, GEMM_SMEM>>>(x, P, TOKP, D_MODEL, D_MODEL, 0);
    }
    // 4. scores = Q @ K^T / 8
    bgemm_kernel<true><<<dim3(SP / 64, SP / 128, NB * HEADS), 256, BG_SMEM_SC>>>(
        q, D_MODEL, (long)SP * D_MODEL, D_HEAD,
        k, D_MODEL, (long)SP * D_MODEL, D_HEAD,
        sc, SP, (long)HEADS * SP * SP, (long)SP * SP,
        SP, SP, D_HEAD, 0.125f);
    // 5. softmax (len 256)
    softmax_kernel<1><<<NB * HEADS * SP, 256>>>(sc, SP);
    // 6. attn = P @ V
    bgemm_kernel<false><<<dim3(1, SP / 128, NB * HEADS), 256, BG_SMEM_PV>>>(
        sc, SP, (long)HEADS * SP * SP, (long)SP * SP,
        v, D_MODEL, (long)SP * D_MODEL, D_HEAD,
        attn, D_MODEL, (long)SP * D_MODEL, D_HEAD,
        SP, D_HEAD, SP, 1.f);
    // 7. p1 = attn @ Wo + bo + prompt
    {
        Ptrs3 P = {{pp_wo, nullptr, nullptr}, {pp_bo, nullptr, nullptr},
                   {prompt, nullptr, nullptr}, {p1, nullptr, nullptr}};
        gemm_bias_kernel<<<dim3(12, 32, 1), 256, GEMM_SMEM>>>(attn, P, TOKP, D_MODEL, D_MODEL, 0);
    }
    // 8. x = LN(p1 + prompt0)
    addln_kernel<<<TOKP, 256>>>(p1, prompt0, ln2g, ln2b, x);
    // 9. xi = LN(image + posi)
    addln_kernel<<<TOKI, 256>>>(image, posi, lnig, lnib, xi);
    // 10. cross Q projection
    {
        Ptrs3 P = {{pi_wq, nullptr, nullptr}, {pi_bq, nullptr, nullptr},
                   {nullptr, nullptr, nullptr}, {q, nullptr, nullptr}};
        gemm_bias_kernel<<<dim3(12, 32, 1), 256, GEMM_SMEM>>>(x, P, TOKP, D_MODEL, D_MODEL, 0);
    }
    // 11. image K,V fused (z = 2)
    {
        Ptrs3 P = {{pi_wk, pi_wv, nullptr}, {pi_bk, pi_bv, nullptr},
                   {nullptr, nullptr, nullptr}, {k, v, nullptr}};
        gemm_bias_kernel<<<dim3(12, 128, 2), 256, GEMM_SMEM>>>(xi, P, TOKI, D_MODEL, D_MODEL, 0);
    }
    // 12. cross scores = Q @ K^T / 8
    bgemm_kernel<true><<<dim3(SI / 64, SP / 128, NB * HEADS), 256, BG_SMEM_SC>>>(
        q, D_MODEL, (long)SP * D_MODEL, D_HEAD,
        k, D_MODEL, (long)SI * D_MODEL, D_HEAD,
        sc, SI, (long)HEADS * SP * SI, (long)SP * SI,
        SP, SI, D_HEAD, 0.125f);
    // 13. softmax (len 1024)
    softmax_kernel<4><<<NB * HEADS * SP, 256>>>(sc, SI);
    // 14. attn = P @ V
    bgemm_kernel<false><<<dim3(1, SP / 128, NB * HEADS), 256, BG_SMEM_PV>>>(
        sc, SI, (long)HEADS * SP * SI, (long)SP * SI,
        v, D_MODEL, (long)SI * D_MODEL, D_HEAD,
        attn, D_MODEL, (long)SP * D_MODEL, D_HEAD,
        SP, D_HEAD, SI, 1.f);
    // 15. p2 = attn @ Wo + bo + p1
    {
        Ptrs3 P = {{pi_wo, nullptr, nullptr}, {pi_bo, nullptr, nullptr},
                   {p1, nullptr, nullptr}, {p2, nullptr, nullptr}};
        gemm_bias_kernel<<<dim3(12, 32, 1), 256, GEMM_SMEM>>>(attn, P, TOKP, D_MODEL, D_MODEL, 0);
    }
    // 16. x = LN(p2 + prompt0)
    addln_kernel<<<TOKP, 256>>>(p2, prompt0, ln3g, ln3b, x);
    // 17. h = relu(x @ W1 + b1)
    {
        Ptrs3 P = {{ff_w1, nullptr, nullptr}, {ff_b1, nullptr, nullptr},
                   {nullptr, nullptr, nullptr}, {hbuf, nullptr, nullptr}};
        gemm_bias_kernel<<<dim3(12, 32, 1), 256, GEMM_SMEM>>>(x, P, TOKP, D_MODEL, D_MODEL, 1);
    }
    // 18. out = h @ W2 + b2
    {
        Ptrs3 P = {{ff_w2, nullptr, nullptr}, {ff_b2, nullptr, nullptr},
                   {nullptr, nullptr, nullptr}, {out, nullptr, nullptr}};
        gemm_bias_kernel<<<dim3(12, 32, 1), 256, GEMM_SMEM>>>(hbuf, P, TOKP, D_MODEL, D_MODEL, 0);
    }
}

// round 4
// speedup vs baseline: 1.1445x; 1.0164x over previous
#include <cuda_runtime.h>
#include <mma.h>
#include <cstdint>

using namespace nvcuda;

#define D_MODEL 768
#define HEADS   12
#define D_HEAD  64
#define NB      16
#define SP      256
#define SI      1024
#define TOKP    (NB*SP)     /* 4096  */
#define TOKI    (NB*SI)     /* 16384 */
#define WELEM   (D_MODEL*D_MODEL)

// ---------------- scratch (device globals: no allocations allowed) ----------------
__device__ float g_prompt0[TOKP*D_MODEL];
__device__ float g_x      [TOKP*D_MODEL];
__device__ float g_xi     [TOKI*D_MODEL];
__device__ float g_q      [TOKP*D_MODEL];
__device__ float g_k      [TOKI*D_MODEL];
__device__ float g_v      [TOKI*D_MODEL];
__device__ float g_scores [(size_t)NB*HEADS*SP*SI];
__device__ float g_attn   [TOKP*D_MODEL];
__device__ float g_p1     [TOKP*D_MODEL];
__device__ float g_p2     [TOKP*D_MODEL];
__device__ float g_h      [TOKP*D_MODEL];
__device__ float g_wr     [10][WELEM];   /* tf32-rounded weights */

// ---------------- helpers ----------------
__device__ __forceinline__ float rtf32(float x) {
    float r; asm("cvt.rna.tf32.f32 %0, %1;" : "=f"(r) : "f"(x)); return r;
}
__device__ __forceinline__ void cp16(float* s, const float* g) {
    uint32_t sa = (uint32_t)__cvta_generic_to_shared(s);
    asm volatile("cp.async.cg.shared.global [%0], [%1], 16;" :: "r"(sa), "l"(g));
}
__device__ __forceinline__ void cp_commit() { asm volatile("cp.async.commit_group;"); }

// ---------------- weight pre-round (fp32 -> tf32 bits in fp32 storage) ----------------
__global__ void round_w_kernel(const float4* __restrict__ src, float4* __restrict__ dst, int n4) {
    int i = blockIdx.x * blockDim.x + threadIdx.x;
    if (i < n4) {
        float4 v = src[i];
        v.x = rtf32(v.x); v.y = rtf32(v.y); v.z = rtf32(v.z); v.w = rtf32(v.w);
        dst[i] = v;
    }
}

// ---------------- elementwise add (float4) ----------------
__global__ void add4_kernel(const float4* __restrict__ a, const float4* __restrict__ b,
                            float4* __restrict__ o, int n4) {
    int i = blockIdx.x * blockDim.x + threadIdx.x;
    if (i < n4) {
        float4 x = a[i], y = b[i];
        x.x += y.x; x.y += y.y; x.z += y.z; x.w += y.w;
        o[i] = x;
    }
}

// ---------------- (optional add) + layernorm; output rounded to tf32 ----------------
__global__ void addln_kernel(const float* __restrict__ a, const float* __restrict__ b,
                             const float* __restrict__ g, const float* __restrict__ be,
                             float* __restrict__ o) {
    int row = blockIdx.x;
    const float* pa = a + (size_t)row * D_MODEL;
    const float* pb = b ? b + (size_t)row * D_MODEL : nullptr;
    float x[3];
    float s = 0.f, sq = 0.f;
#pragma unroll
    for (int j = 0; j < 3; j++) {
        int i = threadIdx.x + j * 256;
        float v = pa[i];
        if (pb) v += pb[i];
        x[j] = v; s += v; sq += v * v;
    }
    __shared__ float sb[16];
    unsigned wid = threadIdx.x >> 5, lane = threadIdx.x & 31;
#pragma unroll
    for (int off = 16; off; off >>= 1) {
        s  += __shfl_xor_sync(0xffffffffu, s,  off);
        sq += __shfl_xor_sync(0xffffffffu, sq, off);
    }
    if (lane == 0) { sb[wid] = s; sb[8 + wid] = sq; }
    __syncthreads();
    if (threadIdx.x < 32) {
        float s2 = (lane < 8) ? sb[lane] : 0.f;
        float q2 = (lane < 8) ? sb[8 + lane] : 0.f;
#pragma unroll
        for (int off = 4; off; off >>= 1) {
            s2 += __shfl_xor_sync(0xffffffffu, s2, off);
            q2 += __shfl_xor_sync(0xffffffffu, q2, off);
        }
        if (lane == 0) { sb[0] = s2; sb[1] = q2; }
    }
    __syncthreads();
    float mean = sb[0] * (1.f / 768.f);
    float var  = sb[1] * (1.f / 768.f) - mean * mean;
    float rs   = rsqrtf(var + 1e-5f);
    float* po = o + (size_t)row * D_MODEL;
#pragma unroll
    for (int j = 0; j < 3; j++) {
        int i = threadIdx.x + j * 256;
        po[i] = rtf32((x[j] - mean) * rs * g[i] + be[i]);
    }
}

// ---------------- row softmax; output rounded to tf32 (feeds PV GEMM) ----------------
template <int PER>
__global__ void softmax_kernel(float* __restrict__ S, int len) {
    size_t row = blockIdx.x;
    float* p = S + row * (size_t)len;
    float v[PER];
    float mx = -3.0e38f;
#pragma unroll
    for (int j = 0; j < PER; j++) {
        v[j] = p[threadIdx.x + j * 256];
        mx = fmaxf(mx, v[j]);
    }
    __shared__ float sb[9];
    unsigned wid = threadIdx.x >> 5, lane = threadIdx.x & 31;
#pragma unroll
    for (int off = 16; off; off >>= 1) mx = fmaxf(mx, __shfl_xor_sync(0xffffffffu, mx, off));
    if (lane == 0) sb[wid] = mx;
    __syncthreads();
    if (threadIdx.x < 32) {
        float m = (lane < 8) ? sb[lane] : -3.0e38f;
#pragma unroll
        for (int off = 4; off; off >>= 1) m = fmaxf(m, __shfl_xor_sync(0xffffffffu, m, off));
        if (lane == 0) sb[8] = m;
    }
    __syncthreads();
    mx = sb[8];
    float sum = 0.f;
#pragma unroll
    for (int j = 0; j < PER; j++) { v[j] = expf(v[j] - mx); sum += v[j]; }
    __syncthreads();
#pragma unroll
    for (int off = 16; off; off >>= 1) sum += __shfl_xor_sync(0xffffffffu, sum, off);
    if (lane == 0) sb[wid] = sum;
    __syncthreads();
    if (threadIdx.x < 32) {
        float m = (lane < 8) ? sb[lane] : 0.f;
#pragma unroll
        for (int off = 4; off; off >>= 1) m += __shfl_xor_sync(0xffffffffu, m, off);
        if (lane == 0) sb[8] = m;
    }
    __syncthreads();
    float inv = 1.f / sb[8];
#pragma unroll
    for (int j = 0; j < PER; j++) p[threadIdx.x + j * 256] = rtf32(v[j] * inv);
}

// ---------------- wmma typedefs ----------------
using FragA  = wmma::fragment<wmma::matrix_a, 16, 16, 8, wmma::precision::tf32, wmma::row_major>;
using FragB  = wmma::fragment<wmma::matrix_b, 16, 16, 8, wmma::precision::tf32, wmma::row_major>;
using FragBT = wmma::fragment<wmma::matrix_b, 16, 16, 8, wmma::precision::tf32, wmma::col_major>;
using FragC  = wmma::fragment<wmma::accumulator, 16, 16, 8, float>;

extern __shared__ float smdyn[];

// ========= dense GEMM: 128x64x32, cp.async 3-stage, warp 32x32, NO in-loop cvt ========
// flags bit0 = relu, bit1 = round output to tf32 (output feeds another GEMM)
struct Ptrs3 {
    const float* W[3];
    const float* Bi[3];
    const float* R[3];
    float* C[3];
    int fl[3];
};

#define G_ALD 36
#define G_BLD 68
#define G_ASZ (128 * G_ALD)      /* 4608 */
#define G_BSZ (32 * G_BLD)       /* 2176 */
#define G_STG (G_ASZ + G_BSZ)    /* 6784 */
#define GEMM_SMEM (3 * G_STG * 4)   /* 81408 bytes */

__global__ __launch_bounds__(256, 2) void gemm_bias_kernel(
    const float* __restrict__ A, Ptrs3 P, int M, int N, int K) {
    const float* W     = P.W[blockIdx.z];
    const float* bias  = P.Bi[blockIdx.z];
    const float* resid = P.R[blockIdx.z];
    float*       C     = P.C[blockIdx.z];
    int flags          = P.fl[blockIdx.z];

    float* As[3] = {smdyn, smdyn + G_STG, smdyn + 2 * G_STG};
    float* Bs[3] = {smdyn + G_ASZ, smdyn + G_STG + G_ASZ, smdyn + 2 * G_STG + G_ASZ};
    int tid = threadIdx.x;
    int m0 = blockIdx.y * 128, n0 = blockIdx.x * 64;
    int warp = tid >> 5, wm = warp & 3, wn = warp >> 2;

    FragC acc[2][2];
#pragma unroll
    for (int i = 0; i < 2; i++)
#pragma unroll
        for (int j = 0; j < 2; j++) wmma::fill_fragment(acc[i][j], 0.f);

    auto load_tile = [&](int s, int k0) {
#pragma unroll
        for (int i = 0; i < 4; i++) {
            int p = tid + i * 256, r = p >> 3, c = (p & 7) * 4;
            cp16(&As[s][r * G_ALD + c], &A[(size_t)(m0 + r) * K + k0 + c]);
        }
#pragma unroll
        for (int i = 0; i < 2; i++) {
            int p = tid + i * 256, r = p >> 4, c = (p & 15) * 4;
            cp16(&Bs[s][r * G_BLD + c], &W[(size_t)(k0 + r) * N + n0 + c]);
        }
        cp_commit();
    };

    int nk = K / 32;
    load_tile(0, 0);
    if (nk > 1) load_tile(1, 32);
    for (int kt = 0; kt < nk; kt++) {
        int s = kt % 3;
        if (kt + 2 < nk) {
            load_tile((kt + 2) % 3, (kt + 2) * 32);
            asm volatile("cp.async.wait_group 2;");
        } else if (kt + 1 < nk) {
            asm volatile("cp.async.wait_group 1;");
        } else {
            asm volatile("cp.async.wait_group 0;");
        }
        __syncthreads();
#pragma unroll
        for (int kk = 0; kk < 32; kk += 8) {
            FragA fa[2]; FragB fb[2];
#pragma unroll
            for (int i = 0; i < 2; i++)
                wmma::load_matrix_sync(fa[i], &As[s][(wm * 32 + i * 16) * G_ALD + kk], G_ALD);
#pragma unroll
            for (int j = 0; j < 2; j++)
                wmma::load_matrix_sync(fb[j], &Bs[s][kk * G_BLD + wn * 32 + j * 16], G_BLD);
#pragma unroll
            for (int i = 0; i < 2; i++)
#pragma unroll
                for (int j = 0; j < 2; j++) wmma::mma_sync(acc[i][j], fa[i], fb[j], acc[i][j]);
        }
        __syncthreads();
    }
    // epilogue staged through smem
    float* Cs = smdyn;
#pragma unroll
    for (int i = 0; i < 2; i++)
#pragma unroll
        for (int j = 0; j < 2; j++)
            wmma::store_matrix_sync(&Cs[(wm * 32 + i * 16) * G_BLD + wn * 32 + j * 16],
                                    acc[i][j], G_BLD, wmma::mem_row_major);
    __syncthreads();
#pragma unroll
    for (int i = 0; i < 8; i++) {
        int p = tid + i * 256, r = p >> 4, c = (p & 15) * 4;
        float4 v = *(float4*)&Cs[r * G_BLD + c];
        int gc = n0 + c;
        float4 bv = *(const float4*)&bias[gc];
        v.x += bv.x; v.y += bv.y; v.z += bv.z; v.w += bv.w;
        size_t off = (size_t)(m0 + r) * N + gc;
        if (resid) {
            float4 rv = *(const float4*)&resid[off];
            v.x += rv.x; v.y += rv.y; v.z += rv.z; v.w += rv.w;
        }
        if (flags & 1) {
            v.x = fmaxf(v.x, 0.f); v.y = fmaxf(v.y, 0.f);
            v.z = fmaxf(v.z, 0.f); v.w = fmaxf(v.w, 0.f);
        }
        if (flags & 2) {
            v.x = rtf32(v.x); v.y = rtf32(v.y); v.z = rtf32(v.z); v.w = rtf32(v.w);
        }
        *(float4*)&C[off] = v;
    }
}

// ======= batched strided GEMM (attention): 128x64x32, 2-stage, NO in-loop cvt =======
// BT: C = A @ B^T (scores).  !BT: C = A @ B (probs @ V).
template <bool BT>
__global__ __launch_bounds__(256, 2) void bgemm_kernel(
    const float* __restrict__ A, int lda, long sAb, long sAh,
    const float* __restrict__ Bm, int ldb, long sBb, long sBh,
    float* __restrict__ C, int ldc, long sCb, long sCh,
    int M, int N, int K, float alpha, int round_out) {
    constexpr int ALD = 36;
    constexpr int BROWS = BT ? 64 : 32;
    constexpr int BLD = BT ? 36 : 68;
    constexpr int ASZ = 128 * ALD;
    constexpr int BSZ = BROWS * BLD;
    constexpr int STG = ASZ + BSZ;

    int z = blockIdx.z, bi = z / HEADS, hi = z % HEADS;
    const float* Ab = A  + (size_t)bi * sAb + (size_t)hi * sAh;
    const float* Bb = Bm + (size_t)bi * sBb + (size_t)hi * sBh;
    float*       Cb = C  + (size_t)bi * sCb + (size_t)hi * sCh;

    float* As[2] = {smdyn,         smdyn + STG};
    float* Bs[2] = {smdyn + ASZ,   smdyn + STG + ASZ};
    int tid = threadIdx.x;
    int m0 = blockIdx.y * 128, n0 = blockIdx.x * 64;
    int warp = tid >> 5, wm = warp & 3, wn = warp >> 2;

    FragC acc[2][2];
#pragma unroll
    for (int i = 0; i < 2; i++)
#pragma unroll
        for (int j = 0; j < 2; j++) wmma::fill_fragment(acc[i][j], 0.f);

    auto load_tile = [&](int s, int k0) {
#pragma unroll
        for (int i = 0; i < 4; i++) {
            int p = tid + i * 256, r = p >> 3, c = (p & 7) * 4;
            cp16(&As[s][r * ALD + c], &Ab[(size_t)(m0 + r) * lda + k0 + c]);
        }
        if (BT) {
#pragma unroll
            for (int i = 0; i < 2; i++) {
                int p = tid + i * 256, r = p >> 3, c = (p & 7) * 4;   // 64 rows x 32
                cp16(&Bs[s][r * BLD + c], &Bb[(size_t)(n0 + r) * ldb + k0 + c]);
            }
        } else {
#pragma unroll
            for (int i = 0; i < 2; i++) {
                int p = tid + i * 256, r = p >> 4, c = (p & 15) * 4;  // 32 rows x 64
                cp16(&Bs[s][r * BLD + c], &Bb[(size_t)(k0 + r) * ldb + n0 + c]);
            }
        }
        cp_commit();
    };

    int nk = K / 32;
    load_tile(0, 0);
    for (int kt = 0; kt < nk; kt++) {
        int s = kt & 1;
        if (kt + 1 < nk) {
            load_tile(s ^ 1, (kt + 1) * 32);
            asm volatile("cp.async.wait_group 1;");
        } else {
            asm volatile("cp.async.wait_group 0;");
        }
        __syncthreads();
#pragma unroll
        for (int kk = 0; kk < 32; kk += 8) {
            FragA fa[2];
#pragma unroll
            for (int i = 0; i < 2; i++)
                wmma::load_matrix_sync(fa[i], &As[s][(wm * 32 + i * 16) * ALD + kk], ALD);
            if (BT) {
                FragBT fb[2];
#pragma unroll
                for (int j = 0; j < 2; j++)
                    wmma::load_matrix_sync(fb[j], &Bs[s][(wn * 32 + j * 16) * BLD + kk], BLD);
#pragma unroll
                for (int i = 0; i < 2; i++)
#pragma unroll
                    for (int j = 0; j < 2; j++) wmma::mma_sync(acc[i][j], fa[i], fb[j], acc[i][j]);
            } else {
                FragB fb[2];
#pragma unroll
                for (int j = 0; j < 2; j++)
                    wmma::load_matrix_sync(fb[j], &Bs[s][kk * BLD + wn * 32 + j * 16], BLD);
#pragma unroll
                for (int i = 0; i < 2; i++)
#pragma unroll
                    for (int j = 0; j < 2; j++) wmma::mma_sync(acc[i][j], fa[i], fb[j], acc[i][j]);
            }
        }
        __syncthreads();
    }
    constexpr int CLDL = 68;
    float* Cs = smdyn;
#pragma unroll
    for (int i = 0; i < 2; i++)
#pragma unroll
        for (int j = 0; j < 2; j++)
            wmma::store_matrix_sync(&Cs[(wm * 32 + i * 16) * CLDL + wn * 32 + j * 16],
                                    acc[i][j], CLDL, wmma::mem_row_major);
    __syncthreads();
#pragma unroll
    for (int i = 0; i < 8; i++) {
        int p = tid + i * 256, r = p >> 4, c = (p & 15) * 4;
        float4 v = *(float4*)&Cs[r * CLDL + c];
        v.x *= alpha; v.y *= alpha; v.z *= alpha; v.w *= alpha;
        if (round_out) {
            v.x = rtf32(v.x); v.y = rtf32(v.y); v.z = rtf32(v.z); v.w = rtf32(v.w);
        }
        *(float4*)&Cb[(size_t)(m0 + r) * ldc + n0 + c] = v;
    }
}

#define BG_SMEM_SC ((128*36 + 64*36) * 2 * 4)   /* 55296 */
#define BG_SMEM_PV ((128*36 + 32*68) * 2 * 4)   /* 54272 */

// ---------------- launcher ----------------
extern "C" void kernel_launch(void* const* d_in, const int* in_sizes, int n_in,
                              void* d_out, int out_size) {
    (void)in_sizes; (void)n_in; (void)out_size;
    const float* image  = (const float*)d_in[0];
    const float* prompt = (const float*)d_in[1];
    const float* posi   = (const float*)d_in[2];
    const float* posp   = (const float*)d_in[3];
    const float* ln1g = (const float*)d_in[4],  *ln1b = (const float*)d_in[5];
    const float* ln2g = (const float*)d_in[6],  *ln2b = (const float*)d_in[7];
    const float* ln3g = (const float*)d_in[8],  *ln3b = (const float*)d_in[9];
    const float* lnig = (const float*)d_in[10], *lnib = (const float*)d_in[11];
    const float* pp_wq = (const float*)d_in[12], *pp_bq = (const float*)d_in[13];
    const float* pp_wk = (const float*)d_in[14], *pp_bk = (const float*)d_in[15];
    const float* pp_wv = (const float*)d_in[16], *pp_bv = (const float*)d_in[17];
    const float* pp_wo = (const float*)d_in[18], *pp_bo = (const float*)d_in[19];
    const float* pi_wq = (const float*)d_in[20], *pi_bq = (const float*)d_in[21];
    const float* pi_wk = (const float*)d_in[22], *pi_bk = (const float*)d_in[23];
    const float* pi_wv = (const float*)d_in[24], *pi_bv = (const float*)d_in[25];
    const float* pi_wo = (const float*)d_in[26], *pi_bo = (const float*)d_in[27];
    const float* ff_w1 = (const float*)d_in[28], *ff_b1 = (const float*)d_in[29];
    const float* ff_w2 = (const float*)d_in[30], *ff_b2 = (const float*)d_in[31];
    float* out = (float*)d_out;

    float *prompt0, *x, *xi, *q, *k, *v, *sc, *attn, *p1, *p2, *hbuf, *wr;
    cudaGetSymbolAddress((void**)&prompt0, g_prompt0);
    cudaGetSymbolAddress((void**)&x,       g_x);
    cudaGetSymbolAddress((void**)&xi,      g_xi);
    cudaGetSymbolAddress((void**)&q,       g_q);
    cudaGetSymbolAddress((void**)&k,       g_k);
    cudaGetSymbolAddress((void**)&v,       g_v);
    cudaGetSymbolAddress((void**)&sc,      g_scores);
    cudaGetSymbolAddress((void**)&attn,    g_attn);
    cudaGetSymbolAddress((void**)&p1,      g_p1);
    cudaGetSymbolAddress((void**)&p2,      g_p2);
    cudaGetSymbolAddress((void**)&hbuf,    g_h);
    cudaGetSymbolAddress((void**)&wr,      g_wr);

    float* rw[10];
    const float* srcw[10] = {pp_wq, pp_wk, pp_wv, pp_wo, pi_wq, pi_wk, pi_wv, pi_wo, ff_w1, ff_w2};
    for (int i = 0; i < 10; i++) rw[i] = wr + (size_t)i * WELEM;

    cudaFuncSetAttribute(gemm_bias_kernel, cudaFuncAttributeMaxDynamicSharedMemorySize, GEMM_SMEM);
    cudaFuncSetAttribute(bgemm_kernel<true>,  cudaFuncAttributeMaxDynamicSharedMemorySize, BG_SMEM_SC);
    cudaFuncSetAttribute(bgemm_kernel<false>, cudaFuncAttributeMaxDynamicSharedMemorySize, BG_SMEM_PV);

    // 0. round all weights to tf32 (10 launches, trivial cost)
    for (int i = 0; i < 10; i++)
        round_w_kernel<<<(WELEM / 4 + 255) / 256, 256>>>((const float4*)srcw[i], (float4*)rw[i], WELEM / 4);

    // 1. prompt0 = prompt + posp
    add4_kernel<<<(TOKP * D_MODEL / 4 + 255) / 256, 256>>>(
        (const float4*)prompt, (const float4*)posp, (float4*)prompt0, TOKP * D_MODEL / 4);
    // 2. x = LN(prompt0)   [tf32-rounded]
    addln_kernel<<<TOKP, 256>>>(prompt0, nullptr, ln1g, ln1b, x);
    // 3. self-attn QKV fused (z = 3), outputs rounded (feed score/PV GEMMs)
    {
        Ptrs3 P = {{rw[0], rw[1], rw[2]}, {pp_bq, pp_bk, pp_bv},
                   {nullptr, nullptr, nullptr}, {q, k, v}, {2, 2, 2}};
        gemm_bias_kernel<<<dim3(12, 32, 3), 256, GEMM_SMEM>>>(x, P, TOKP, D_MODEL, D_MODEL);
    }
    // 4. scores = Q @ K^T / 8
    bgemm_kernel<true><<<dim3(SP / 64, SP / 128, NB * HEADS), 256, BG_SMEM_SC>>>(
        q, D_MODEL, (long)SP * D_MODEL, D_HEAD,
        k, D_MODEL, (long)SP * D_MODEL, D_HEAD,
        sc, SP, (long)HEADS * SP * SP, (long)SP * SP,
        SP, SP, D_HEAD, 0.125f, 0);
    // 5. softmax (len 256) [probs tf32-rounded]
    softmax_kernel<1><<<NB * HEADS * SP, 256>>>(sc, SP);
    // 6. attn = P @ V   [rounded: feeds Wo GEMM]
    bgemm_kernel<false><<<dim3(1, SP / 128, NB * HEADS), 256, BG_SMEM_PV>>>(
        sc, SP, (long)HEADS * SP * SP, (long)SP * SP,
        v, D_MODEL, (long)SP * D_MODEL, D_HEAD,
        attn, D_MODEL, (long)SP * D_MODEL, D_HEAD,
        SP, D_HEAD, SP, 1.f, 1);
    // 7. p1 = attn @ Wo + bo + prompt   [fp32, feeds LN]
    {
        Ptrs3 P = {{rw[3], nullptr, nullptr}, {pp_bo, nullptr, nullptr},
                   {prompt, nullptr, nullptr}, {p1, nullptr, nullptr}, {0, 0, 0}};
        gemm_bias_kernel<<<dim3(12, 32, 1), 256, GEMM_SMEM>>>(attn, P, TOKP, D_MODEL, D_MODEL);
    }
    // 8. x = LN(p1 + prompt0)
    addln_kernel<<<TOKP, 256>>>(p1, prompt0, ln2g, ln2b, x);
    // 9. xi = LN(image + posi)
    addln_kernel<<<TOKI, 256>>>(image, posi, lnig, lnib, xi);
    // 10. cross Q projection [rounded]
    {
        Ptrs3 P = {{rw[4], nullptr, nullptr}, {pi_bq, nullptr, nullptr},
                   {nullptr, nullptr, nullptr}, {q, nullptr, nullptr}, {2, 0, 0}};
        gemm_bias_kernel<<<dim3(12, 32, 1), 256, GEMM_SMEM>>>(x, P, TOKP, D_MODEL, D_MODEL);
    }
    // 11. image K,V fused (z = 2) [rounded]
    {
        Ptrs3 P = {{rw[5], rw[6], nullptr}, {pi_bk, pi_bv, nullptr},
                   {nullptr, nullptr, nullptr}, {k, v, nullptr}, {2, 2, 0}};
        gemm_bias_kernel<<<dim3(12, 128, 2), 256, GEMM_SMEM>>>(xi, P, TOKI, D_MODEL, D_MODEL);
    }
    // 12. cross scores = Q @ K^T / 8
    bgemm_kernel<true><<<dim3(SI / 64, SP / 128, NB * HEADS), 256, BG_SMEM_SC>>>(
        q, D_MODEL, (long)SP * D_MODEL, D_HEAD,
        k, D_MODEL, (long)SI * D_MODEL, D_HEAD,
        sc, SI, (long)HEADS * SP * SI, (long)SP * SI,
        SP, SI, D_HEAD, 0.125f, 0);
    // 13. softmax (len 1024)
    softmax_kernel<4><<<NB * HEADS * SP, 256>>>(sc, SI);
    // 14. attn = P @ V [rounded]
    bgemm_kernel<false><<<dim3(1, SP / 128, NB * HEADS), 256, BG_SMEM_PV>>>(
        sc, SI, (long)HEADS * SP * SI, (long)SP * SI,
        v, D_MODEL, (long)SI * D_MODEL, D_HEAD,
        attn, D_MODEL, (long)SP * D_MODEL, D_HEAD,
        SP, D_HEAD, SI, 1.f, 1);
    // 15. p2 = attn @ Wo + bo + p1 [fp32]
    {
        Ptrs3 P = {{rw[7], nullptr, nullptr}, {pi_bo, nullptr, nullptr},
                   {p1, nullptr, nullptr}, {p2, nullptr, nullptr}, {0, 0, 0}};
        gemm_bias_kernel<<<dim3(12, 32, 1), 256, GEMM_SMEM>>>(attn, P, TOKP, D_MODEL, D_MODEL);
    }
    // 16. x = LN(p2 + prompt0)
    addln_kernel<<<TOKP, 256>>>(p2, prompt0, ln3g, ln3b, x);
    // 17. h = relu(x @ W1 + b1) [relu + rounded]
    {
        Ptrs3 P = {{rw[8], nullptr, nullptr}, {ff_b1, nullptr, nullptr},
                   {nullptr, nullptr, nullptr}, {hbuf, nullptr, nullptr}, {3, 0, 0}};
        gemm_bias_kernel<<<dim3(12, 32, 1), 256, GEMM_SMEM>>>(x, P, TOKP, D_MODEL, D_MODEL);
    }
    // 18. out = h @ W2 + b2 [fp32 final]
    {
        Ptrs3 P = {{rw[9], nullptr, nullptr}, {ff_b2, nullptr, nullptr},
                   {nullptr, nullptr, nullptr}, {out, nullptr, nullptr}, {0, 0, 0}};
        gemm_bias_kernel<<<dim3(12, 32, 1), 256, GEMM_SMEM>>>(hbuf, P, TOKP, D_MODEL, D_MODEL);
    }
}

// round 6
// speedup vs baseline: 1.1604x; 1.0139x over previous
#include <cuda_runtime.h>
#include <mma.h>
#include <cstdint>

using namespace nvcuda;

#define D_MODEL 768
#define HEADS   12
#define D_HEAD  64
#define NB      16
#define SP      256
#define SI      1024
#define TOKP    (NB*SP)     /* 4096  */
#define TOKI    (NB*SI)     /* 16384 */
#define WELEM   (D_MODEL*D_MODEL)

// ---------------- scratch (device globals: no allocations allowed) ----------------
__device__ float g_prompt0[TOKP*D_MODEL];
__device__ float g_x      [TOKP*D_MODEL];
__device__ float g_xi     [TOKI*D_MODEL];
__device__ float g_q      [TOKP*D_MODEL];
__device__ float g_k      [TOKI*D_MODEL];
__device__ float g_v      [TOKI*D_MODEL];
__device__ float g_scores [(size_t)NB*HEADS*SP*SI];
__device__ float g_attn   [TOKP*D_MODEL];
__device__ float g_p1     [TOKP*D_MODEL];
__device__ float g_p2     [TOKP*D_MODEL];
__device__ float g_h      [TOKP*D_MODEL];
__device__ float g_wr     [10][WELEM];   /* tf32-rounded weights */

// ---------------- helpers ----------------
__device__ __forceinline__ float rtf32(float x) {
    float r; asm("cvt.rna.tf32.f32 %0, %1;" : "=f"(r) : "f"(x)); return r;
}
__device__ __forceinline__ void cp16(float* s, const float* g) {
    uint32_t sa = (uint32_t)__cvta_generic_to_shared(s);
    asm volatile("cp.async.cg.shared.global [%0], [%1], 16;" :: "r"(sa), "l"(g));
}
__device__ __forceinline__ void cp_commit() { asm volatile("cp.async.commit_group;"); }

// ---------------- weight pre-round (fp32 -> tf32 bits in fp32 storage) ----------------
__global__ void round_w_kernel(const float4* __restrict__ src, float4* __restrict__ dst, int n4) {
    int i = blockIdx.x * blockDim.x + threadIdx.x;
    if (i < n4) {
        float4 v = src[i];
        v.x = rtf32(v.x); v.y = rtf32(v.y); v.z = rtf32(v.z); v.w = rtf32(v.w);
        dst[i] = v;
    }
}

// ---------------- elementwise add (float4) ----------------
__global__ void add4_kernel(const float4* __restrict__ a, const float4* __restrict__ b,
                            float4* __restrict__ o, int n4) {
    int i = blockIdx.x * blockDim.x + threadIdx.x;
    if (i < n4) {
        float4 x = a[i], y = b[i];
        x.x += y.x; x.y += y.y; x.z += y.z; x.w += y.w;
        o[i] = x;
    }
}

// ---------------- (optional add) + layernorm; output rounded to tf32 ----------------
__global__ void addln_kernel(const float* __restrict__ a, const float* __restrict__ b,
                             const float* __restrict__ g, const float* __restrict__ be,
                             float* __restrict__ o) {
    int row = blockIdx.x;
    const float* pa = a + (size_t)row * D_MODEL;
    const float* pb = b ? b + (size_t)row * D_MODEL : nullptr;
    float x[3];
    float s = 0.f, sq = 0.f;
#pragma unroll
    for (int j = 0; j < 3; j++) {
        int i = threadIdx.x + j * 256;
        float v = pa[i];
        if (pb) v += pb[i];
        x[j] = v; s += v; sq += v * v;
    }
    __shared__ float sb[16];
    unsigned wid = threadIdx.x >> 5, lane = threadIdx.x & 31;
#pragma unroll
    for (int off = 16; off; off >>= 1) {
        s  += __shfl_xor_sync(0xffffffffu, s,  off);
        sq += __shfl_xor_sync(0xffffffffu, sq, off);
    }
    if (lane == 0) { sb[wid] = s; sb[8 + wid] = sq; }
    __syncthreads();
    if (threadIdx.x < 32) {
        float s2 = (lane < 8) ? sb[lane] : 0.f;
        float q2 = (lane < 8) ? sb[8 + lane] : 0.f;
#pragma unroll
        for (int off = 4; off; off >>= 1) {
            s2 += __shfl_xor_sync(0xffffffffu, s2, off);
            q2 += __shfl_xor_sync(0xffffffffu, q2, off);
        }
        if (lane == 0) { sb[0] = s2; sb[1] = q2; }
    }
    __syncthreads();
    float mean = sb[0] * (1.f / 768.f);
    float var  = sb[1] * (1.f / 768.f) - mean * mean;
    float rs   = rsqrtf(var + 1e-5f);
    float* po = o + (size_t)row * D_MODEL;
#pragma unroll
    for (int j = 0; j < 3; j++) {
        int i = threadIdx.x + j * 256;
        po[i] = rtf32((x[j] - mean) * rs * g[i] + be[i]);
    }
}

// ---------------- row softmax; output rounded to tf32 ----------------
template <int PER>
__global__ void softmax_kernel(float* __restrict__ S, int len) {
    size_t row = blockIdx.x;
    float* p = S + row * (size_t)len;
    float v[PER];
    float mx = -3.0e38f;
#pragma unroll
    for (int j = 0; j < PER; j++) {
        v[j] = p[threadIdx.x + j * 256];
        mx = fmaxf(mx, v[j]);
    }
    __shared__ float sb[9];
    unsigned wid = threadIdx.x >> 5, lane = threadIdx.x & 31;
#pragma unroll
    for (int off = 16; off; off >>= 1) mx = fmaxf(mx, __shfl_xor_sync(0xffffffffu, mx, off));
    if (lane == 0) sb[wid] = mx;
    __syncthreads();
    if (threadIdx.x < 32) {
        float m = (lane < 8) ? sb[lane] : -3.0e38f;
#pragma unroll
        for (int off = 4; off; off >>= 1) m = fmaxf(m, __shfl_xor_sync(0xffffffffu, m, off));
        if (lane == 0) sb[8] = m;
    }
    __syncthreads();
    mx = sb[8];
    float sum = 0.f;
#pragma unroll
    for (int j = 0; j < PER; j++) { v[j] = expf(v[j] - mx); sum += v[j]; }
    __syncthreads();
#pragma unroll
    for (int off = 16; off; off >>= 1) sum += __shfl_xor_sync(0xffffffffu, sum, off);
    if (lane == 0) sb[wid] = sum;
    __syncthreads();
    if (threadIdx.x < 32) {
        float m = (lane < 8) ? sb[lane] : 0.f;
#pragma unroll
        for (int off = 4; off; off >>= 1) m += __shfl_xor_sync(0xffffffffu, m, off);
        if (lane == 0) sb[8] = m;
    }
    __syncthreads();
    float inv = 1.f / sb[8];
#pragma unroll
    for (int j = 0; j < PER; j++) p[threadIdx.x + j * 256] = rtf32(v[j] * inv);
}

// ---------------- wmma typedefs ----------------
using FragA  = wmma::fragment<wmma::matrix_a, 16, 16, 8, wmma::precision::tf32, wmma::row_major>;
using FragB  = wmma::fragment<wmma::matrix_b, 16, 16, 8, wmma::precision::tf32, wmma::row_major>;
using FragBT = wmma::fragment<wmma::matrix_b, 16, 16, 8, wmma::precision::tf32, wmma::col_major>;
using FragC  = wmma::fragment<wmma::accumulator, 16, 16, 8, float>;

extern __shared__ float smdyn[];

// ===== dense GEMM: 128x128x32, warp tile 64x32 (8 warps 2x4), cp.async 2-stage =====
// flags bit0 = relu, bit1 = round output to tf32 (feeds another GEMM)
struct Ptrs3 {
    const float* W[3];
    const float* Bi[3];
    const float* R[3];
    float* C[3];
    int fl[3];
};

#define G_ALD 36
#define G_BLD 132
#define G_ASZ (128 * G_ALD)      /* 4608 */
#define G_BSZ (32 * G_BLD)       /* 4224 */
#define G_STG (G_ASZ + G_BSZ)    /* 8832 */
#define GEMM_SMEM (2 * G_STG * 4)   /* 70656 bytes */

__global__ __launch_bounds__(256, 2) void gemm_bias_kernel(
    const float* __restrict__ A, Ptrs3 P, int M, int N, int K) {
    const float* W     = P.W[blockIdx.z];
    const float* bias  = P.Bi[blockIdx.z];
    const float* resid = P.R[blockIdx.z];
    float*       C     = P.C[blockIdx.z];
    int flags          = P.fl[blockIdx.z];

    float* As[2] = {smdyn,          smdyn + G_STG};
    float* Bs[2] = {smdyn + G_ASZ,  smdyn + G_STG + G_ASZ};
    int tid = threadIdx.x;
    int m0 = blockIdx.y * 128, n0 = blockIdx.x * 128;
    int warp = tid >> 5, wm = warp & 1, wn = warp >> 1;   // warp tile 64x32

    FragC acc[4][2];
#pragma unroll
    for (int i = 0; i < 4; i++)
#pragma unroll
        for (int j = 0; j < 2; j++) wmma::fill_fragment(acc[i][j], 0.f);

    auto load_tile = [&](int s, int k0) {
#pragma unroll
        for (int i = 0; i < 4; i++) {
            int p = tid + i * 256, r = p >> 3, c = (p & 7) * 4;
            cp16(&As[s][r * G_ALD + c], &A[(size_t)(m0 + r) * K + k0 + c]);
        }
#pragma unroll
        for (int i = 0; i < 4; i++) {
            int p = tid + i * 256, r = p >> 5, c = (p & 31) * 4;
            cp16(&Bs[s][r * G_BLD + c], &W[(size_t)(k0 + r) * N + n0 + c]);
        }
        cp_commit();
    };

    int nk = K / 32;
    load_tile(0, 0);
    for (int kt = 0; kt < nk; kt++) {
        int s = kt & 1;
        if (kt + 1 < nk) {
            load_tile(s ^ 1, (kt + 1) * 32);
            asm volatile("cp.async.wait_group 1;");
        } else {
            asm volatile("cp.async.wait_group 0;");
        }
        __syncthreads();
#pragma unroll
        for (int kk = 0; kk < 32; kk += 8) {
            FragA fa[4]; FragB fb[2];
#pragma unroll
            for (int i = 0; i < 4; i++)
                wmma::load_matrix_sync(fa[i], &As[s][(wm * 64 + i * 16) * G_ALD + kk], G_ALD);
#pragma unroll
            for (int j = 0; j < 2; j++)
                wmma::load_matrix_sync(fb[j], &Bs[s][kk * G_BLD + wn * 32 + j * 16], G_BLD);
#pragma unroll
            for (int i = 0; i < 4; i++)
#pragma unroll
                for (int j = 0; j < 2; j++) wmma::mma_sync(acc[i][j], fa[i], fb[j], acc[i][j]);
        }
        __syncthreads();
    }
    // epilogue staged through smem (128 x 132)
    float* Cs = smdyn;
#pragma unroll
    for (int i = 0; i < 4; i++)
#pragma unroll
        for (int j = 0; j < 2; j++)
            wmma::store_matrix_sync(&Cs[(wm * 64 + i * 16) * G_BLD + wn * 32 + j * 16],
                                    acc[i][j], G_BLD, wmma::mem_row_major);
    __syncthreads();
#pragma unroll
    for (int i = 0; i < 16; i++) {
        int p = tid + i * 256, r = p >> 5, c = (p & 31) * 4;
        float4 v = *(float4*)&Cs[r * G_BLD + c];
        int gc = n0 + c;
        float4 bv = *(const float4*)&bias[gc];
        v.x += bv.x; v.y += bv.y; v.z += bv.z; v.w += bv.w;
        size_t off = (size_t)(m0 + r) * N + gc;
        if (resid) {
            float4 rv = *(const float4*)&resid[off];
            v.x += rv.x; v.y += rv.y; v.z += rv.z; v.w += rv.w;
        }
        if (flags & 1) {
            v.x = fmaxf(v.x, 0.f); v.y = fmaxf(v.y, 0.f);
            v.z = fmaxf(v.z, 0.f); v.w = fmaxf(v.w, 0.f);
        }
        if (flags & 2) {
            v.x = rtf32(v.x); v.y = rtf32(v.y); v.z = rtf32(v.z); v.w = rtf32(v.w);
        }
        *(float4*)&C[off] = v;
    }
}

// ======= batched strided GEMM (attention): 128x64x32, 2-stage, warp 32x32 =======
template <bool BT>
__global__ __launch_bounds__(256, 2) void bgemm_kernel(
    const float* __restrict__ A, int lda, long sAb, long sAh,
    const float* __restrict__ Bm, int ldb, long sBb, long sBh,
    float* __restrict__ C, int ldc, long sCb, long sCh,
    int M, int N, int K, float alpha, int round_out) {
    constexpr int ALD = 36;
    constexpr int BROWS = BT ? 64 : 32;
    constexpr int BLD = BT ? 36 : 68;
    constexpr int ASZ = 128 * ALD;
    constexpr int BSZ = BROWS * BLD;
    constexpr int STG = ASZ + BSZ;

    int z = blockIdx.z, bi = z / HEADS, hi = z % HEADS;
    const float* Ab = A  + (size_t)bi * sAb + (size_t)hi * sAh;
    const float* Bb = Bm + (size_t)bi * sBb + (size_t)hi * sBh;
    float*       Cb = C  + (size_t)bi * sCb + (size_t)hi * sCh;

    float* As[2] = {smdyn,         smdyn + STG};
    float* Bs[2] = {smdyn + ASZ,   smdyn + STG + ASZ};
    int tid = threadIdx.x;
    int m0 = blockIdx.y * 128, n0 = blockIdx.x * 64;
    int warp = tid >> 5, wm = warp & 3, wn = warp >> 2;

    FragC acc[2][2];
#pragma unroll
    for (int i = 0; i < 2; i++)
#pragma unroll
        for (int j = 0; j < 2; j++) wmma::fill_fragment(acc[i][j], 0.f);

    auto load_tile = [&](int s, int k0) {
#pragma unroll
        for (int i = 0; i < 4; i++) {
            int p = tid + i * 256, r = p >> 3, c = (p & 7) * 4;
            cp16(&As[s][r * ALD + c], &Ab[(size_t)(m0 + r) * lda + k0 + c]);
        }
        if (BT) {
#pragma unroll
            for (int i = 0; i < 2; i++) {
                int p = tid + i * 256, r = p >> 3, c = (p & 7) * 4;
                cp16(&Bs[s][r * BLD + c], &Bb[(size_t)(n0 + r) * ldb + k0 + c]);
            }
        } else {
#pragma unroll
            for (int i = 0; i < 2; i++) {
                int p = tid + i * 256, r = p >> 4, c = (p & 15) * 4;
                cp16(&Bs[s][r * BLD + c], &Bb[(size_t)(k0 + r) * ldb + n0 + c]);
            }
        }
        cp_commit();
    };

    int nk = K / 32;
    load_tile(0, 0);
    for (int kt = 0; kt < nk; kt++) {
        int s = kt & 1;
        if (kt + 1 < nk) {
            load_tile(s ^ 1, (kt + 1) * 32);
            asm volatile("cp.async.wait_group 1;");
        } else {
            asm volatile("cp.async.wait_group 0;");
        }
        __syncthreads();
#pragma unroll
        for (int kk = 0; kk < 32; kk += 8) {
            FragA fa[2];
#pragma unroll
            for (int i = 0; i < 2; i++)
                wmma::load_matrix_sync(fa[i], &As[s][(wm * 32 + i * 16) * ALD + kk], ALD);
            if (BT) {
                FragBT fb[2];
#pragma unroll
                for (int j = 0; j < 2; j++)
                    wmma::load_matrix_sync(fb[j], &Bs[s][(wn * 32 + j * 16) * BLD + kk], BLD);
#pragma unroll
                for (int i = 0; i < 2; i++)
#pragma unroll
                    for (int j = 0; j < 2; j++) wmma::mma_sync(acc[i][j], fa[i], fb[j], acc[i][j]);
            } else {
                FragB fb[2];
#pragma unroll
                for (int j = 0; j < 2; j++)
                    wmma::load_matrix_sync(fb[j], &Bs[s][kk * BLD + wn * 32 + j * 16], BLD);
#pragma unroll
                for (int i = 0; i < 2; i++)
#pragma unroll
                    for (int j = 0; j < 2; j++) wmma::mma_sync(acc[i][j], fa[i], fb[j], acc[i][j]);
            }
        }
        __syncthreads();
    }
    constexpr int CLDL = 68;
    float* Cs = smdyn;
#pragma unroll
    for (int i = 0; i < 2; i++)
#pragma unroll
        for (int j = 0; j < 2; j++)
            wmma::store_matrix_sync(&Cs[(wm * 32 + i * 16) * CLDL + wn * 32 + j * 16],
                                    acc[i][j], CLDL, wmma::mem_row_major);
    __syncthreads();
#pragma unroll
    for (int i = 0; i < 8; i++) {
        int p = tid + i * 256, r = p >> 4, c = (p & 15) * 4;
        float4 v = *(float4*)&Cs[r * CLDL + c];
        v.x *= alpha; v.y *= alpha; v.z *= alpha; v.w *= alpha;
        if (round_out) {
            v.x = rtf32(v.x); v.y = rtf32(v.y); v.z = rtf32(v.z); v.w = rtf32(v.w);
        }
        *(float4*)&Cb[(size_t)(m0 + r) * ldc + n0 + c] = v;
    }
}

#define BG_SMEM_SC ((128*36 + 64*36) * 2 * 4)   /* 55296 */
#define BG_SMEM_PV ((128*36 + 32*68) * 2 * 4)   /* 54272 */

// ---------------- launcher ----------------
extern "C" void kernel_launch(void* const* d_in, const int* in_sizes, int n_in,
                              void* d_out, int out_size) {
    (void)in_sizes; (void)n_in; (void)out_size;
    const float* image  = (const float*)d_in[0];
    const float* prompt = (const float*)d_in[1];
    const float* posi   = (const float*)d_in[2];
    const float* posp   = (const float*)d_in[3];
    const float* ln1g = (const float*)d_in[4],  *ln1b = (const float*)d_in[5];
    const float* ln2g = (const float*)d_in[6],  *ln2b = (const float*)d_in[7];
    const float* ln3g = (const float*)d_in[8],  *ln3b = (const float*)d_in[9];
    const float* lnig = (const float*)d_in[10], *lnib = (const float*)d_in[11];
    const float* pp_wq = (const float*)d_in[12], *pp_bq = (const float*)d_in[13];
    const float* pp_wk = (const float*)d_in[14], *pp_bk = (const float*)d_in[15];
    const float* pp_wv = (const float*)d_in[16], *pp_bv = (const float*)d_in[17];
    const float* pp_wo = (const float*)d_in[18], *pp_bo = (const float*)d_in[19];
    const float* pi_wq = (const float*)d_in[20], *pi_bq = (const float*)d_in[21];
    const float* pi_wk = (const float*)d_in[22], *pi_bk = (const float*)d_in[23];
    const float* pi_wv = (const float*)d_in[24], *pi_bv = (const float*)d_in[25];
    const float* pi_wo = (const float*)d_in[26], *pi_bo = (const float*)d_in[27];
    const float* ff_w1 = (const float*)d_in[28], *ff_b1 = (const float*)d_in[29];
    const float* ff_w2 = (const float*)d_in[30], *ff_b2 = (const float*)d_in[31];
    float* out = (float*)d_out;

    float *prompt0, *x, *xi, *q, *k, *v, *sc, *attn, *p1, *p2, *hbuf, *wr;
    cudaGetSymbolAddress((void**)&prompt0, g_prompt0);
    cudaGetSymbolAddress((void**)&x,       g_x);
    cudaGetSymbolAddress((void**)&xi,      g_xi);
    cudaGetSymbolAddress((void**)&q,       g_q);
    cudaGetSymbolAddress((void**)&k,       g_k);
    cudaGetSymbolAddress((void**)&v,       g_v);
    cudaGetSymbolAddress((void**)&sc,      g_scores);
    cudaGetSymbolAddress((void**)&attn,    g_attn);
    cudaGetSymbolAddress((void**)&p1,      g_p1);
    cudaGetSymbolAddress((void**)&p2,      g_p2);
    cudaGetSymbolAddress((void**)&hbuf,    g_h);
    cudaGetSymbolAddress((void**)&wr,      g_wr);

    float* rw[10];
    const float* srcw[10] = {pp_wq, pp_wk, pp_wv, pp_wo, pi_wq, pi_wk, pi_wv, pi_wo, ff_w1, ff_w2};
    for (int i = 0; i < 10; i++) rw[i] = wr + (size_t)i * WELEM;

    cudaFuncSetAttribute(gemm_bias_kernel, cudaFuncAttributeMaxDynamicSharedMemorySize, GEMM_SMEM);
    cudaFuncSetAttribute(bgemm_kernel<true>,  cudaFuncAttributeMaxDynamicSharedMemorySize, BG_SMEM_SC);
    cudaFuncSetAttribute(bgemm_kernel<false>, cudaFuncAttributeMaxDynamicSharedMemorySize, BG_SMEM_PV);

    // 0. round all weights to tf32
    for (int i = 0; i < 10; i++)
        round_w_kernel<<<(WELEM / 4 + 255) / 256, 256>>>((const float4*)srcw[i], (float4*)rw[i], WELEM / 4);

    // 1. prompt0 = prompt + posp
    add4_kernel<<<(TOKP * D_MODEL / 4 + 255) / 256, 256>>>(
        (const float4*)prompt, (const float4*)posp, (float4*)prompt0, TOKP * D_MODEL / 4);
    // 2. x = LN(prompt0)   [tf32-rounded]
    addln_kernel<<<TOKP, 256>>>(prompt0, nullptr, ln1g, ln1b, x);
    // 3. self-attn QKV fused (z = 3), outputs rounded
    {
        Ptrs3 P = {{rw[0], rw[1], rw[2]}, {pp_bq, pp_bk, pp_bv},
                   {nullptr, nullptr, nullptr}, {q, k, v}, {2, 2, 2}};
        gemm_bias_kernel<<<dim3(6, 32, 3), 256, GEMM_SMEM>>>(x, P, TOKP, D_MODEL, D_MODEL);
    }
    // 4. scores = Q @ K^T / 8
    bgemm_kernel<true><<<dim3(SP / 64, SP / 128, NB * HEADS), 256, BG_SMEM_SC>>>(
        q, D_MODEL, (long)SP * D_MODEL, D_HEAD,
        k, D_MODEL, (long)SP * D_MODEL, D_HEAD,
        sc, SP, (long)HEADS * SP * SP, (long)SP * SP,
        SP, SP, D_HEAD, 0.125f, 0);
    // 5. softmax (len 256) [tf32-rounded]
    softmax_kernel<1><<<NB * HEADS * SP, 256>>>(sc, SP);
    // 6. attn = P @ V [rounded: feeds Wo GEMM]
    bgemm_kernel<false><<<dim3(1, SP / 128, NB * HEADS), 256, BG_SMEM_PV>>>(
        sc, SP, (long)HEADS * SP * SP, (long)SP * SP,
        v, D_MODEL, (long)SP * D_MODEL, D_HEAD,
        attn, D_MODEL, (long)SP * D_MODEL, D_HEAD,
        SP, D_HEAD, SP, 1.f, 1);
    // 7. p1 = attn @ Wo + bo + prompt
    {
        Ptrs3 P = {{rw[3], nullptr, nullptr}, {pp_bo, nullptr, nullptr},
                   {prompt, nullptr, nullptr}, {p1, nullptr, nullptr}, {0, 0, 0}};
        gemm_bias_kernel<<<dim3(6, 32, 1), 256, GEMM_SMEM>>>(attn, P, TOKP, D_MODEL, D_MODEL);
    }
    // 8. x = LN(p1 + prompt0)
    addln_kernel<<<TOKP, 256>>>(p1, prompt0, ln2g, ln2b, x);
    // 9. xi = LN(image + posi)
    addln_kernel<<<TOKI, 256>>>(image, posi, lnig, lnib, xi);
    // 10. cross Q projection [rounded]
    {
        Ptrs3 P = {{rw[4], nullptr, nullptr}, {pi_bq, nullptr, nullptr},
                   {nullptr, nullptr, nullptr}, {q, nullptr, nullptr}, {2, 0, 0}};
        gemm_bias_kernel<<<dim3(6, 32, 1), 256, GEMM_SMEM>>>(x, P, TOKP, D_MODEL, D_MODEL);
    }
    // 11. image K,V fused (z = 2) [rounded]
    {
        Ptrs3 P = {{rw[5], rw[6], nullptr}, {pi_bk, pi_bv, nullptr},
                   {nullptr, nullptr, nullptr}, {k, v, nullptr}, {2, 2, 0}};
        gemm_bias_kernel<<<dim3(6, 128, 2), 256, GEMM_SMEM>>>(xi, P, TOKI, D_MODEL, D_MODEL);
    }
    // 12. cross scores = Q @ K^T / 8
    bgemm_kernel<true><<<dim3(SI / 64, SP / 128, NB * HEADS), 256, BG_SMEM_SC>>>(
        q, D_MODEL, (long)SP * D_MODEL, D_HEAD,
        k, D_MODEL, (long)SI * D_MODEL, D_HEAD,
        sc, SI, (long)HEADS * SP * SI, (long)SP * SI,
        SP, SI, D_HEAD, 0.125f, 0);
    // 13. softmax (len 1024)
    softmax_kernel<4><<<NB * HEADS * SP, 256>>>(sc, SI);
    // 14. attn = P @ V [rounded]
    bgemm_kernel<false><<<dim3(1, SP / 128, NB * HEADS), 256, BG_SMEM_PV>>>(
        sc, SI, (long)HEADS * SP * SI, (long)SP * SI,
        v, D_MODEL, (long)SI * D_MODEL, D_HEAD,
        attn, D_MODEL, (long)SP * D_MODEL, D_HEAD,
        SP, D_HEAD, SI, 1.f, 1);
    // 15. p2 = attn @ Wo + bo + p1
    {
        Ptrs3 P = {{rw[7], nullptr, nullptr}, {pi_bo, nullptr, nullptr},
                   {p1, nullptr, nullptr}, {p2, nullptr, nullptr}, {0, 0, 0}};
        gemm_bias_kernel<<<dim3(6, 32, 1), 256, GEMM_SMEM>>>(attn, P, TOKP, D_MODEL, D_MODEL);
    }
    // 16. x = LN(p2 + prompt0)
    addln_kernel<<<TOKP, 256>>>(p2, prompt0, ln3g, ln3b, x);
    // 17. h = relu(x @ W1 + b1) [relu + rounded]
    {
        Ptrs3 P = {{rw[8], nullptr, nullptr}, {ff_b1, nullptr, nullptr},
                   {nullptr, nullptr, nullptr}, {hbuf, nullptr, nullptr}, {3, 0, 0}};
        gemm_bias_kernel<<<dim3(6, 32, 1), 256, GEMM_SMEM>>>(x, P, TOKP, D_MODEL, D_MODEL);
    }
    // 18. out = h @ W2 + b2
    {
        Ptrs3 P = {{rw[9], nullptr, nullptr}, {ff_b2, nullptr, nullptr},
                   {nullptr, nullptr, nullptr}, {out, nullptr, nullptr}, {0, 0, 0}};
        gemm_bias_kernel<<<dim3(6, 32, 1), 256, GEMM_SMEM>>>(hbuf, P, TOKP, D_MODEL, D_MODEL);
    }
}

// round 8
// speedup vs baseline: 2.7898x; 2.4041x over previous
#include <cuda_runtime.h>
#include <cuda_fp16.h>
#include <mma.h>
#include <cstdint>

using namespace nvcuda;

#define D_MODEL 768
#define HEADS   12
#define D_HEAD  64
#define NB      16
#define SP      256
#define SI      1024
#define TOKP    (NB*SP)     /* 4096  */
#define TOKI    (NB*SI)     /* 16384 */
#define WELEM   (D_MODEL*D_MODEL)

// ---------------- scratch (device globals: no allocations allowed) ----------------
__device__ float  g_prompt0[TOKP*D_MODEL];
__device__ float  g_scores [(size_t)NB*HEADS*SP*SI];
__device__ float  g_p1     [TOKP*D_MODEL];
__device__ float  g_p2     [TOKP*D_MODEL];
__device__ __half g_x   [TOKP*D_MODEL];
__device__ __half g_xi  [TOKI*D_MODEL];
__device__ __half g_q   [TOKP*D_MODEL];
__device__ __half g_k   [TOKI*D_MODEL];
__device__ __half g_v   [TOKI*D_MODEL];
__device__ __half g_probs[(size_t)NB*HEADS*SP*SI];
__device__ __half g_attn[TOKP*D_MODEL];
__device__ __half g_h   [TOKP*D_MODEL];
__device__ __half g_wh  [10][WELEM];   /* fp16 weights, [k][n] layout */

// ---------------- helpers ----------------
__device__ __forceinline__ void cpa16(uint32_t sa, const void* g) {
    asm volatile("cp.async.cg.shared.global [%0], [%1], 16;" :: "r"(sa), "l"(g));
}
__device__ __forceinline__ void cp_commit() { asm volatile("cp.async.commit_group;"); }
__device__ __forceinline__ uint32_t su32(const void* p) {
    return (uint32_t)__cvta_generic_to_shared(p);
}

// ---------------- weight fp32 -> fp16 ----------------
__global__ void half_w_kernel(const float4* __restrict__ src, __half* __restrict__ dst, int n4) {
    int i = blockIdx.x * blockDim.x + threadIdx.x;
    if (i < n4) {
        float4 v = src[i];
        __half2 a = __floats2half2_rn(v.x, v.y);
        __half2 b = __floats2half2_rn(v.z, v.w);
        *(__half2*)&dst[i * 4]     = a;
        *(__half2*)&dst[i * 4 + 2] = b;
    }
}

// ---------------- elementwise add (float4) ----------------
__global__ void add4_kernel(const float4* __restrict__ a, const float4* __restrict__ b,
                            float4* __restrict__ o, int n4) {
    int i = blockIdx.x * blockDim.x + threadIdx.x;
    if (i < n4) {
        float4 x = a[i], y = b[i];
        x.x += y.x; x.y += y.y; x.z += y.z; x.w += y.w;
        o[i] = x;
    }
}

// ---------------- (optional add) + layernorm -> fp16 ----------------
__global__ void addln_kernel(const float* __restrict__ a, const float* __restrict__ b,
                             const float* __restrict__ g, const float* __restrict__ be,
                             __half* __restrict__ o) {
    int row = blockIdx.x;
    const float* pa = a + (size_t)row * D_MODEL;
    const float* pb = b ? b + (size_t)row * D_MODEL : nullptr;
    float x[3];
    float s = 0.f, sq = 0.f;
#pragma unroll
    for (int j = 0; j < 3; j++) {
        int i = threadIdx.x + j * 256;
        float v = pa[i];
        if (pb) v += pb[i];
        x[j] = v; s += v; sq += v * v;
    }
    __shared__ float sb[16];
    unsigned wid = threadIdx.x >> 5, lane = threadIdx.x & 31;
#pragma unroll
    for (int off = 16; off; off >>= 1) {
        s  += __shfl_xor_sync(0xffffffffu, s,  off);
        sq += __shfl_xor_sync(0xffffffffu, sq, off);
    }
    if (lane == 0) { sb[wid] = s; sb[8 + wid] = sq; }
    __syncthreads();
    if (threadIdx.x < 32) {
        float s2 = (lane < 8) ? sb[lane] : 0.f;
        float q2 = (lane < 8) ? sb[8 + lane] : 0.f;
#pragma unroll
        for (int off = 4; off; off >>= 1) {
            s2 += __shfl_xor_sync(0xffffffffu, s2, off);
            q2 += __shfl_xor_sync(0xffffffffu, q2, off);
        }
        if (lane == 0) { sb[0] = s2; sb[1] = q2; }
    }
    __syncthreads();
    float mean = sb[0] * (1.f / 768.f);
    float var  = sb[1] * (1.f / 768.f) - mean * mean;
    float rs   = rsqrtf(var + 1e-5f);
#pragma unroll
    for (int j = 0; j < 3; j++) {
        int i = threadIdx.x + j * 256;
        o[(size_t)row * D_MODEL + i] = __float2half_rn((x[j] - mean) * rs * g[i] + be[i]);
    }
}

// ---------------- row softmax: fp32 scores -> fp16 probs ----------------
template <int PER>
__global__ void softmax_kernel(const float* __restrict__ S, __half* __restrict__ P, int len) {
    size_t row = blockIdx.x;
    const float* p = S + row * (size_t)len;
    __half* po = P + row * (size_t)len;
    float v[PER];
    float mx = -3.0e38f;
#pragma unroll
    for (int j = 0; j < PER; j++) {
        v[j] = p[threadIdx.x + j * 256];
        mx = fmaxf(mx, v[j]);
    }
    __shared__ float sb[9];
    unsigned wid = threadIdx.x >> 5, lane = threadIdx.x & 31;
#pragma unroll
    for (int off = 16; off; off >>= 1) mx = fmaxf(mx, __shfl_xor_sync(0xffffffffu, mx, off));
    if (lane == 0) sb[wid] = mx;
    __syncthreads();
    if (threadIdx.x < 32) {
        float m = (lane < 8) ? sb[lane] : -3.0e38f;
#pragma unroll
        for (int off = 4; off; off >>= 1) m = fmaxf(m, __shfl_xor_sync(0xffffffffu, m, off));
        if (lane == 0) sb[8] = m;
    }
    __syncthreads();
    mx = sb[8];
    float sum = 0.f;
#pragma unroll
    for (int j = 0; j < PER; j++) { v[j] = expf(v[j] - mx); sum += v[j]; }
    __syncthreads();
#pragma unroll
    for (int off = 16; off; off >>= 1) sum += __shfl_xor_sync(0xffffffffu, sum, off);
    if (lane == 0) sb[wid] = sum;
    __syncthreads();
    if (threadIdx.x < 32) {
        float m = (lane < 8) ? sb[lane] : 0.f;
#pragma unroll
        for (int off = 4; off; off >>= 1) m += __shfl_xor_sync(0xffffffffu, m, off);
        if (lane == 0) sb[8] = m;
    }
    __syncthreads();
    float inv = 1.f / sb[8];
#pragma unroll
    for (int j = 0; j < PER; j++) po[threadIdx.x + j * 256] = __float2half_rn(v[j] * inv);
}

// ---------------- wmma fp16 typedefs ----------------
using HFragA  = wmma::fragment<wmma::matrix_a, 16, 16, 16, __half, wmma::row_major>;
using HFragB  = wmma::fragment<wmma::matrix_b, 16, 16, 16, __half, wmma::row_major>;
using HFragBT = wmma::fragment<wmma::matrix_b, 16, 16, 16, __half, wmma::col_major>;
using HFragC  = wmma::fragment<wmma::accumulator, 16, 16, 16, float>;

extern __shared__ __align__(16) char smraw[];

// ===== dense GEMM: 128x128xK64 fp16, warp 64x32 (8 warps 2x4), cp.async 2-stage =====
// flags bit0 = relu, bit1 = fp16 output (else fp32)
struct DZ {
    const __half* W[3];
    const float*  Bi[3];
    const float*  R[3];
    float*  Cf[3];
    __half* Ch[3];
    int fl[3];
};

#define D_ALD 72                     /* halves: 64 + 8 pad */
#define D_BLD 136                    /* halves: 128 + 8 pad */
#define D_ASZ (128 * D_ALD)          /* 9216 halves */
#define D_BSZ (64 * D_BLD)           /* 8704 halves */
#define D_STG (D_ASZ + D_BSZ)        /* 17920 halves = 35840 B */
#define D_CLD 132
#define DENSE_SMEM (2 * D_STG * 2)   /* 71680 B; epilogue 128*132*4=67584 fits */

__global__ __launch_bounds__(256, 2) void dense_gemm_kernel(
    const __half* __restrict__ A, DZ P, int M) {
    constexpr int K = D_MODEL, N = D_MODEL;
    const __half* W    = P.W[blockIdx.z];
    const float* bias  = P.Bi[blockIdx.z];
    const float* resid = P.R[blockIdx.z];
    float*  Cf         = P.Cf[blockIdx.z];
    __half* Ch         = P.Ch[blockIdx.z];
    int flags          = P.fl[blockIdx.z];

    __half* sm = (__half*)smraw;
    __half* As[2] = {sm,         sm + D_STG};
    __half* Bs[2] = {sm + D_ASZ, sm + D_STG + D_ASZ};
    int tid = threadIdx.x;
    int m0 = blockIdx.y * 128, n0 = blockIdx.x * 128;
    int warp = tid >> 5, wm = warp & 1, wn = warp >> 1;   // warp tile 64x32

    HFragC acc[4][2];
#pragma unroll
    for (int i = 0; i < 4; i++)
#pragma unroll
        for (int j = 0; j < 2; j++) wmma::fill_fragment(acc[i][j], 0.f);

    auto load_tile = [&](int s, int k0) {
#pragma unroll
        for (int i = 0; i < 4; i++) {           // A: 128 rows x 8 chunks = 1024 chunks
            int p = tid + i * 256, r = p >> 3, c = (p & 7) * 8;
            cpa16(su32(&As[s][r * D_ALD + c]), &A[(size_t)(m0 + r) * K + k0 + c]);
        }
#pragma unroll
        for (int i = 0; i < 4; i++) {           // B: 64 rows x 16 chunks = 1024 chunks
            int p = tid + i * 256, r = p >> 4, c = (p & 15) * 8;
            cpa16(su32(&Bs[s][r * D_BLD + c]), &W[(size_t)(k0 + r) * N + n0 + c]);
        }
        cp_commit();
    };

    const int nk = K / 64;   // 12
    load_tile(0, 0);
    for (int kt = 0; kt < nk; kt++) {
        int s = kt & 1;
        if (kt + 1 < nk) {
            load_tile(s ^ 1, (kt + 1) * 64);
            asm volatile("cp.async.wait_group 1;");
        } else {
            asm volatile("cp.async.wait_group 0;");
        }
        __syncthreads();
#pragma unroll
        for (int kk = 0; kk < 64; kk += 16) {
            HFragA fa[4]; HFragB fb[2];
#pragma unroll
            for (int i = 0; i < 4; i++)
                wmma::load_matrix_sync(fa[i], &As[s][(wm * 64 + i * 16) * D_ALD + kk], D_ALD);
#pragma unroll
            for (int j = 0; j < 2; j++)
                wmma::load_matrix_sync(fb[j], &Bs[s][kk * D_BLD + wn * 32 + j * 16], D_BLD);
#pragma unroll
            for (int i = 0; i < 4; i++)
#pragma unroll
                for (int j = 0; j < 2; j++) wmma::mma_sync(acc[i][j], fa[i], fb[j], acc[i][j]);
        }
        __syncthreads();
    }
    // epilogue staged through smem (fp32 128x132)
    float* Cs = (float*)smraw;
#pragma unroll
    for (int i = 0; i < 4; i++)
#pragma unroll
        for (int j = 0; j < 2; j++)
            wmma::store_matrix_sync(&Cs[(wm * 64 + i * 16) * D_CLD + wn * 32 + j * 16],
                                    acc[i][j], D_CLD, wmma::mem_row_major);
    __syncthreads();
#pragma unroll
    for (int i = 0; i < 16; i++) {
        int p = tid + i * 256, r = p >> 5, c = (p & 31) * 4;
        float4 v = *(float4*)&Cs[r * D_CLD + c];
        int gc = n0 + c;
        float4 bv = *(const float4*)&bias[gc];
        v.x += bv.x; v.y += bv.y; v.z += bv.z; v.w += bv.w;
        size_t off = (size_t)(m0 + r) * N + gc;
        if (resid) {
            float4 rv = *(const float4*)&resid[off];
            v.x += rv.x; v.y += rv.y; v.z += rv.z; v.w += rv.w;
        }
        if (flags & 1) {
            v.x = fmaxf(v.x, 0.f); v.y = fmaxf(v.y, 0.f);
            v.z = fmaxf(v.z, 0.f); v.w = fmaxf(v.w, 0.f);
        }
        if (flags & 2) {
            *(__half2*)&Ch[off]     = __floats2half2_rn(v.x, v.y);
            *(__half2*)&Ch[off + 2] = __floats2half2_rn(v.z, v.w);
        } else {
            *(float4*)&Cf[off] = v;
        }
    }
}

// ===== scores: C = Q @ K^T * alpha, single-shot K=64, fp16 in, fp32 out =====
#define SC_LD 72
#define SC_SMEM (((128 + 64) * SC_LD * 2 > 128 * 68 * 4) ? ((128 + 64) * SC_LD * 2) : (128 * 68 * 4))

__global__ __launch_bounds__(256, 2) void score_gemm_kernel(
    const __half* __restrict__ Q, const __half* __restrict__ Km,
    float* __restrict__ C, int ldk_tokens, float alpha) {
    int z = blockIdx.z, bi = z / HEADS, hi = z % HEADS;
    const __half* Qb = Q  + (size_t)bi * SP * D_MODEL + hi * D_HEAD;
    const __half* Kb = Km + (size_t)bi * ldk_tokens * D_MODEL + hi * D_HEAD;
    float* Cb = C + (size_t)z * SP * ldk_tokens;

    __half* sm = (__half*)smraw;
    __half* Aq = sm;                 // [128][72]
    __half* Bk = sm + 128 * SC_LD;   // [64][72]
    int tid = threadIdx.x;
    int m0 = blockIdx.y * 128, n0 = blockIdx.x * 64;
    int warp = tid >> 5, wm = warp & 3, wn = warp >> 2;

#pragma unroll
    for (int i = 0; i < 4; i++) {        // Q: 128 rows x 8 chunks = 1024
        int p = tid + i * 256, r = p >> 3, c = (p & 7) * 8;
        cpa16(su32(&Aq[r * SC_LD + c]), &Qb[(size_t)(m0 + r) * D_MODEL + c]);
    }
#pragma unroll
    for (int i = 0; i < 2; i++) {        // K: 64 rows x 8 chunks = 512
        int p = tid + i * 256, r = p >> 3, c = (p & 7) * 8;
        cpa16(su32(&Bk[r * SC_LD + c]), &Kb[(size_t)(n0 + r) * D_MODEL + c]);
    }
    cp_commit();
    asm volatile("cp.async.wait_group 0;");
    __syncthreads();

    HFragC acc[2][2];
#pragma unroll
    for (int i = 0; i < 2; i++)
#pragma unroll
        for (int j = 0; j < 2; j++) wmma::fill_fragment(acc[i][j], 0.f);
#pragma unroll
    for (int kk = 0; kk < 64; kk += 16) {
        HFragA fa[2]; HFragBT fb[2];
#pragma unroll
        for (int i = 0; i < 2; i++)
            wmma::load_matrix_sync(fa[i], &Aq[(wm * 32 + i * 16) * SC_LD + kk], SC_LD);
#pragma unroll
        for (int j = 0; j < 2; j++)
            wmma::load_matrix_sync(fb[j], &Bk[(wn * 32 + j * 16) * SC_LD + kk], SC_LD);
#pragma unroll
        for (int i = 0; i < 2; i++)
#pragma unroll
            for (int j = 0; j < 2; j++) wmma::mma_sync(acc[i][j], fa[i], fb[j], acc[i][j]);
    }
    __syncthreads();
    float* Cs = (float*)smraw;
#pragma unroll
    for (int i = 0; i < 2; i++)
#pragma unroll
        for (int j = 0; j < 2; j++)
            wmma::store_matrix_sync(&Cs[(wm * 32 + i * 16) * 68 + wn * 32 + j * 16],
                                    acc[i][j], 68, wmma::mem_row_major);
    __syncthreads();
#pragma unroll
    for (int i = 0; i < 8; i++) {
        int p = tid + i * 256, r = p >> 4, c = (p & 15) * 4;
        float4 v = *(float4*)&Cs[r * 68 + c];
        v.x *= alpha; v.y *= alpha; v.z *= alpha; v.w *= alpha;
        *(float4*)&Cb[(size_t)(m0 + r) * ldk_tokens + n0 + c] = v;
    }
}

// ===== PV: attn = probs @ V, fp16 in/out, K-tile 64, 2-stage =====
#define PV_ALD 72
#define PV_BLD 72
#define PV_ASZ (128 * PV_ALD)
#define PV_BSZ (64 * PV_BLD)
#define PV_STG (PV_ASZ + PV_BSZ)
#define PV_SMEM ((2 * PV_STG * 2 > 128 * 68 * 4) ? (2 * PV_STG * 2) : (128 * 68 * 4))

__global__ __launch_bounds__(256, 2) void pv_gemm_kernel(
    const __half* __restrict__ Pm, const __half* __restrict__ V,
    __half* __restrict__ O, int kv_tokens) {
    int z = blockIdx.z, bi = z / HEADS, hi = z % HEADS;
    const __half* Pb = Pm + (size_t)z * SP * kv_tokens;
    const __half* Vb = V + (size_t)bi * kv_tokens * D_MODEL + hi * D_HEAD;
    __half* Ob = O + (size_t)bi * SP * D_MODEL + hi * D_HEAD;

    __half* sm = (__half*)smraw;
    __half* As[2] = {sm,          sm + PV_STG};
    __half* Bs[2] = {sm + PV_ASZ, sm + PV_STG + PV_ASZ};
    int tid = threadIdx.x;
    int m0 = blockIdx.y * 128;
    int warp = tid >> 5, wm = warp & 3, wn = warp >> 2;

    HFragC acc[2][2];
#pragma unroll
    for (int i = 0; i < 2; i++)
#pragma unroll
        for (int j = 0; j < 2; j++) wmma::fill_fragment(acc[i][j], 0.f);

    auto load_tile = [&](int s, int k0) {
#pragma unroll
        for (int i = 0; i < 4; i++) {         // probs: 128 rows x 8 chunks = 1024
            int p = tid + i * 256, r = p >> 3, c = (p & 7) * 8;
            cpa16(su32(&As[s][r * PV_ALD + c]), &Pb[(size_t)(m0 + r) * kv_tokens + k0 + c]);
        }
#pragma unroll
        for (int i = 0; i < 2; i++) {         // V: 64 rows x 8 chunks = 512
            int p = tid + i * 256, r = p >> 3, c = (p & 7) * 8;
            cpa16(su32(&Bs[s][r * PV_BLD + c]), &Vb[(size_t)(k0 + r) * D_MODEL + c]);
        }
        cp_commit();
    };

    int nk = kv_tokens / 64;
    load_tile(0, 0);
    for (int kt = 0; kt < nk; kt++) {
        int s = kt & 1;
        if (kt + 1 < nk) {
            load_tile(s ^ 1, (kt + 1) * 64);
            asm volatile("cp.async.wait_group 1;");
        } else {
            asm volatile("cp.async.wait_group 0;");
        }
        __syncthreads();
#pragma unroll
        for (int kk = 0; kk < 64; kk += 16) {
            HFragA fa[2]; HFragB fb[2];
#pragma unroll
            for (int i = 0; i < 2; i++)
                wmma::load_matrix_sync(fa[i], &As[s][(wm * 32 + i * 16) * PV_ALD + kk], PV_ALD);
#pragma unroll
            for (int j = 0; j < 2; j++)
                wmma::load_matrix_sync(fb[j], &Bs[s][kk * PV_BLD + wn * 32 + j * 16], PV_BLD);
#pragma unroll
            for (int i = 0; i < 2; i++)
#pragma unroll
                for (int j = 0; j < 2; j++) wmma::mma_sync(acc[i][j], fa[i], fb[j], acc[i][j]);
        }
        __syncthreads();
    }
    float* Cs = (float*)smraw;
#pragma unroll
    for (int i = 0; i < 2; i++)
#pragma unroll
        for (int j = 0; j < 2; j++)
            wmma::store_matrix_sync(&Cs[(wm * 32 + i * 16) * 68 + wn * 32 + j * 16],
                                    acc[i][j], 68, wmma::mem_row_major);
    __syncthreads();
#pragma unroll
    for (int i = 0; i < 8; i++) {
        int p = tid + i * 256, r = p >> 4, c = (p & 15) * 4;
        float4 v = *(float4*)&Cs[r * 68 + c];
        size_t off = (size_t)(m0 + r) * D_MODEL + c;
        *(__half2*)&Ob[off]     = __floats2half2_rn(v.x, v.y);
        *(__half2*)&Ob[off + 2] = __floats2half2_rn(v.z, v.w);
    }
}

// ---------------- launcher ----------------
extern "C" void kernel_launch(void* const* d_in, const int* in_sizes, int n_in,
                              void* d_out, int out_size) {
    (void)in_sizes; (void)n_in; (void)out_size;
    const float* image  = (const float*)d_in[0];
    const float* prompt = (const float*)d_in[1];
    const float* posi   = (const float*)d_in[2];
    const float* posp   = (const float*)d_in[3];
    const float* ln1g = (const float*)d_in[4],  *ln1b = (const float*)d_in[5];
    const float* ln2g = (const float*)d_in[6],  *ln2b = (const float*)d_in[7];
    const float* ln3g = (const float*)d_in[8],  *ln3b = (const float*)d_in[9];
    const float* lnig = (const float*)d_in[10], *lnib = (const float*)d_in[11];
    const float* pp_wq = (const float*)d_in[12], *pp_bq = (const float*)d_in[13];
    const float* pp_wk = (const float*)d_in[14], *pp_bk = (const float*)d_in[15];
    const float* pp_wv = (const float*)d_in[16], *pp_bv = (const float*)d_in[17];
    const float* pp_wo = (const float*)d_in[18], *pp_bo = (const float*)d_in[19];
    const float* pi_wq = (const float*)d_in[20], *pi_bq = (const float*)d_in[21];
    const float* pi_wk = (const float*)d_in[22], *pi_bk = (const float*)d_in[23];
    const float* pi_wv = (const float*)d_in[24], *pi_bv = (const float*)d_in[25];
    const float* pi_wo = (const float*)d_in[26], *pi_bo = (const float*)d_in[27];
    const float* ff_w1 = (const float*)d_in[28], *ff_b1 = (const float*)d_in[29];
    const float* ff_w2 = (const float*)d_in[30], *ff_b2 = (const float*)d_in[31];
    float* out = (float*)d_out;

    float *prompt0, *sc, *p1, *p2;
    __half *x, *xi, *q, *k, *v, *probs, *attn, *h, *wh;
    cudaGetSymbolAddress((void**)&prompt0, g_prompt0);
    cudaGetSymbolAddress((void**)&sc,    g_scores);
    cudaGetSymbolAddress((void**)&p1,    g_p1);
    cudaGetSymbolAddress((void**)&p2,    g_p2);
    cudaGetSymbolAddress((void**)&x,     g_x);
    cudaGetSymbolAddress((void**)&xi,    g_xi);
    cudaGetSymbolAddress((void**)&q,     g_q);
    cudaGetSymbolAddress((void**)&k,     g_k);
    cudaGetSymbolAddress((void**)&v,     g_v);
    cudaGetSymbolAddress((void**)&probs, g_probs);
    cudaGetSymbolAddress((void**)&attn,  g_attn);
    cudaGetSymbolAddress((void**)&h,     g_h);
    cudaGetSymbolAddress((void**)&wh,    g_wh);

    __half* W[10];
    const float* srcw[10] = {pp_wq, pp_wk, pp_wv, pp_wo, pi_wq, pi_wk, pi_wv, pi_wo, ff_w1, ff_w2};
    for (int i = 0; i < 10; i++) W[i] = wh + (size_t)i * WELEM;

    cudaFuncSetAttribute(dense_gemm_kernel, cudaFuncAttributeMaxDynamicSharedMemorySize, DENSE_SMEM);
    cudaFuncSetAttribute(score_gemm_kernel, cudaFuncAttributeMaxDynamicSharedMemorySize, SC_SMEM);
    cudaFuncSetAttribute(pv_gemm_kernel,    cudaFuncAttributeMaxDynamicSharedMemorySize, PV_SMEM);

    // 0. weights -> fp16
    for (int i = 0; i < 10; i++)
        half_w_kernel<<<(WELEM / 4 + 255) / 256, 256>>>((const float4*)srcw[i], W[i], WELEM / 4);

    // 1. prompt0 = prompt + posp
    add4_kernel<<<(TOKP * D_MODEL / 4 + 255) / 256, 256>>>(
        (const float4*)prompt, (const float4*)posp, (float4*)prompt0, TOKP * D_MODEL / 4);
    // 2. x = LN(prompt0) -> fp16
    addln_kernel<<<TOKP, 256>>>(prompt0, nullptr, ln1g, ln1b, x);
    // 3. self QKV fused (z=3) -> fp16
    {
        DZ P = {{W[0], W[1], W[2]}, {pp_bq, pp_bk, pp_bv}, {nullptr, nullptr, nullptr},
                {nullptr, nullptr, nullptr}, {q, k, v}, {2, 2, 2}};
        dense_gemm_kernel<<<dim3(6, 32, 3), 256, DENSE_SMEM>>>(x, P, TOKP);
    }
    // 4. scores = Q @ K^T / 8 (fp32)
    score_gemm_kernel<<<dim3(SP / 64, SP / 128, NB * HEADS), 256, SC_SMEM>>>(q, k, sc, SP, 0.125f);
    // 5. softmax -> fp16 probs
    softmax_kernel<1><<<NB * HEADS * SP, 256>>>(sc, probs, SP);
    // 6. attn = P @ V -> fp16
    pv_gemm_kernel<<<dim3(1, SP / 128, NB * HEADS), 256, PV_SMEM>>>(probs, v, attn, SP);
    // 7. p1 = attn @ Wo + bo + prompt (fp32)
    {
        DZ P = {{W[3], nullptr, nullptr}, {pp_bo, nullptr, nullptr}, {prompt, nullptr, nullptr},
                {p1, nullptr, nullptr}, {nullptr, nullptr, nullptr}, {0, 0, 0}};
        dense_gemm_kernel<<<dim3(6, 32, 1), 256, DENSE_SMEM>>>(attn, P, TOKP);
    }
    // 8. x = LN(p1 + prompt0) -> fp16
    addln_kernel<<<TOKP, 256>>>(p1, prompt0, ln2g, ln2b, x);
    // 9. xi = LN(image + posi) -> fp16
    addln_kernel<<<TOKI, 256>>>(image, posi, lnig, lnib, xi);
    // 10. cross Q -> fp16
    {
        DZ P = {{W[4], nullptr, nullptr}, {pi_bq, nullptr, nullptr}, {nullptr, nullptr, nullptr},
                {nullptr, nullptr, nullptr}, {q, nullptr, nullptr}, {2, 0, 0}};
        dense_gemm_kernel<<<dim3(6, 32, 1), 256, DENSE_SMEM>>>(x, P, TOKP);
    }
    // 11. image K,V fused (z=2) -> fp16
    {
        DZ P = {{W[5], W[6], nullptr}, {pi_bk, pi_bv, nullptr}, {nullptr, nullptr, nullptr},
                {nullptr, nullptr, nullptr}, {k, v, nullptr}, {2, 2, 0}};
        dense_gemm_kernel<<<dim3(6, 128, 2), 256, DENSE_SMEM>>>(xi, P, TOKI);
    }
    // 12. cross scores
    score_gemm_kernel<<<dim3(SI / 64, SP / 128, NB * HEADS), 256, SC_SMEM>>>(q, k, sc, SI, 0.125f);
    // 13. softmax -> fp16
    softmax_kernel<4><<<NB * HEADS * SP, 256>>>(sc, probs, SI);
    // 14. attn = P @ V -> fp16
    pv_gemm_kernel<<<dim3(1, SP / 128, NB * HEADS), 256, PV_SMEM>>>(probs, v, attn, SI);
    // 15. p2 = attn @ Wo + bo + p1 (fp32)
    {
        DZ P = {{W[7], nullptr, nullptr}, {pi_bo, nullptr, nullptr}, {p1, nullptr, nullptr},
                {p2, nullptr, nullptr}, {nullptr, nullptr, nullptr}, {0, 0, 0}};
        dense_gemm_kernel<<<dim3(6, 32, 1), 256, DENSE_SMEM>>>(attn, P, TOKP);
    }
    // 16. x = LN(p2 + prompt0) -> fp16
    addln_kernel<<<TOKP, 256>>>(p2, prompt0, ln3g, ln3b, x);
    // 17. h = relu(x @ W1 + b1) -> fp16
    {
        DZ P = {{W[8], nullptr, nullptr}, {ff_b1, nullptr, nullptr}, {nullptr, nullptr, nullptr},
                {nullptr, nullptr, nullptr}, {h, nullptr, nullptr}, {3, 0, 0}};
        dense_gemm_kernel<<<dim3(6, 32, 1), 256, DENSE_SMEM>>>(x, P, TOKP);
    }
    // 18. out = h @ W2 + b2 (fp32 final)
    {
        DZ P = {{W[9], nullptr, nullptr}, {ff_b2, nullptr, nullptr}, {nullptr, nullptr, nullptr},
                {out, nullptr, nullptr}, {nullptr, nullptr, nullptr}, {0, 0, 0}};
        dense_gemm_kernel<<<dim3(6, 32, 1), 256, DENSE_SMEM>>>(h, P, TOKP);
    }
}

// round 10
// speedup vs baseline: 3.1714x; 1.1368x over previous
#include <cuda_runtime.h>
#include <cuda_fp16.h>
#include <mma.h>
#include <cstdint>

using namespace nvcuda;

#define D_MODEL 768
#define HEADS   12
#define D_HEAD  64
#define NB      16
#define SP      256
#define SI      1024
#define TOKP    (NB*SP)     /* 4096  */
#define TOKI    (NB*SI)     /* 16384 */
#define WELEM   (D_MODEL*D_MODEL)

// ---------------- scratch (device globals: no allocations allowed) ----------------
__device__ float  g_prompt0[TOKP*D_MODEL];
__device__ float  g_p1     [TOKP*D_MODEL];
__device__ float  g_p2     [TOKP*D_MODEL];
__device__ __half g_x   [TOKP*D_MODEL];
__device__ __half g_xi  [TOKI*D_MODEL];
__device__ __half g_q   [TOKP*D_MODEL];
__device__ __half g_k   [TOKI*D_MODEL];
__device__ __half g_v   [TOKI*D_MODEL];
__device__ __half g_attn[TOKP*D_MODEL];
__device__ __half g_h   [TOKP*D_MODEL];
__device__ __half g_wh  [10][WELEM];   /* fp16 weights, [k][n] layout */

// ---------------- helpers ----------------
__device__ __forceinline__ void cpa16(uint32_t sa, const void* g) {
    asm volatile("cp.async.cg.shared.global [%0], [%1], 16;" :: "r"(sa), "l"(g));
}
__device__ __forceinline__ void cp_commit() { asm volatile("cp.async.commit_group;"); }
__device__ __forceinline__ uint32_t su32(const void* p) {
    return (uint32_t)__cvta_generic_to_shared(p);
}

// ---------------- fused weight fp32 -> fp16 (all 10 matrices, one launch) ----------------
struct WSrc { const float* p[10]; };
__global__ void half_w_all_kernel(WSrc S, __half* __restrict__ dst) {
    int mat = blockIdx.y;
    int i = blockIdx.x * blockDim.x + threadIdx.x;   // float4 index within matrix
    const float4* s = (const float4*)S.p[mat];
    float4 v = s[i];
    __half* d = dst + (size_t)mat * WELEM + (size_t)i * 4;
    *(__half2*)&d[0] = __floats2half2_rn(v.x, v.y);
    *(__half2*)&d[2] = __floats2half2_rn(v.z, v.w);
}

// ---------------- elementwise add (float4) ----------------
__global__ void add4_kernel(const float4* __restrict__ a, const float4* __restrict__ b,
                            float4* __restrict__ o, int n4) {
    int i = blockIdx.x * blockDim.x + threadIdx.x;
    if (i < n4) {
        float4 x = a[i], y = b[i];
        x.x += y.x; x.y += y.y; x.z += y.z; x.w += y.w;
        o[i] = x;
    }
}

// ---------------- (optional add) + layernorm -> fp16 ----------------
__global__ void addln_kernel(const float* __restrict__ a, const float* __restrict__ b,
                             const float* __restrict__ g, const float* __restrict__ be,
                             __half* __restrict__ o) {
    int row = blockIdx.x;
    const float* pa = a + (size_t)row * D_MODEL;
    const float* pb = b ? b + (size_t)row * D_MODEL : nullptr;
    float x[3];
    float s = 0.f, sq = 0.f;
#pragma unroll
    for (int j = 0; j < 3; j++) {
        int i = threadIdx.x + j * 256;
        float v = pa[i];
        if (pb) v += pb[i];
        x[j] = v; s += v; sq += v * v;
    }
    __shared__ float sb[16];
    unsigned wid = threadIdx.x >> 5, lane = threadIdx.x & 31;
#pragma unroll
    for (int off = 16; off; off >>= 1) {
        s  += __shfl_xor_sync(0xffffffffu, s,  off);
        sq += __shfl_xor_sync(0xffffffffu, sq, off);
    }
    if (lane == 0) { sb[wid] = s; sb[8 + wid] = sq; }
    __syncthreads();
    if (threadIdx.x < 32) {
        float s2 = (lane < 8) ? sb[lane] : 0.f;
        float q2 = (lane < 8) ? sb[8 + lane] : 0.f;
#pragma unroll
        for (int off = 4; off; off >>= 1) {
            s2 += __shfl_xor_sync(0xffffffffu, s2, off);
            q2 += __shfl_xor_sync(0xffffffffu, q2, off);
        }
        if (lane == 0) { sb[0] = s2; sb[1] = q2; }
    }
    __syncthreads();
    float mean = sb[0] * (1.f / 768.f);
    float var  = sb[1] * (1.f / 768.f) - mean * mean;
    float rs   = rsqrtf(var + 1e-5f);
#pragma unroll
    for (int j = 0; j < 3; j++) {
        int i = threadIdx.x + j * 256;
        o[(size_t)row * D_MODEL + i] = __float2half_rn((x[j] - mean) * rs * g[i] + be[i]);
    }
}

// ---------------- wmma fp16 typedefs ----------------
using HFragA  = wmma::fragment<wmma::matrix_a, 16, 16, 16, __half, wmma::row_major>;
using HFragB  = wmma::fragment<wmma::matrix_b, 16, 16, 16, __half, wmma::row_major>;
using HFragBT = wmma::fragment<wmma::matrix_b, 16, 16, 16, __half, wmma::col_major>;
using HFragC  = wmma::fragment<wmma::accumulator, 16, 16, 16, float>;

extern __shared__ __align__(16) char smraw[];

// ===== dense GEMM: 128x128xK64 fp16, warp 64x32 (8 warps 2x4), cp.async 2-stage =====
// flags bit0 = relu, bit1 = fp16 output (else fp32)
struct DZ {
    const __half* W[3];
    const float*  Bi[3];
    const float*  R[3];
    float*  Cf[3];
    __half* Ch[3];
    int fl[3];
};

#define D_ALD 72
#define D_BLD 136
#define D_ASZ (128 * D_ALD)
#define D_BSZ (64 * D_BLD)
#define D_STG (D_ASZ + D_BSZ)
#define D_CLD 132
#define DENSE_SMEM (2 * D_STG * 2)   /* 71680 B */

__global__ __launch_bounds__(256, 2) void dense_gemm_kernel(
    const __half* __restrict__ A, DZ P, int M) {
    constexpr int K = D_MODEL, N = D_MODEL;
    const __half* W    = P.W[blockIdx.z];
    const float* bias  = P.Bi[blockIdx.z];
    const float* resid = P.R[blockIdx.z];
    float*  Cf         = P.Cf[blockIdx.z];
    __half* Ch         = P.Ch[blockIdx.z];
    int flags          = P.fl[blockIdx.z];

    __half* sm = (__half*)smraw;
    __half* As[2] = {sm,         sm + D_STG};
    __half* Bs[2] = {sm + D_ASZ, sm + D_STG + D_ASZ};
    int tid = threadIdx.x;
    int m0 = blockIdx.y * 128, n0 = blockIdx.x * 128;
    int warp = tid >> 5, wm = warp & 1, wn = warp >> 1;

    HFragC acc[4][2];
#pragma unroll
    for (int i = 0; i < 4; i++)
#pragma unroll
        for (int j = 0; j < 2; j++) wmma::fill_fragment(acc[i][j], 0.f);

    auto load_tile = [&](int s, int k0) {
#pragma unroll
        for (int i = 0; i < 4; i++) {
            int p = tid + i * 256, r = p >> 3, c = (p & 7) * 8;
            cpa16(su32(&As[s][r * D_ALD + c]), &A[(size_t)(m0 + r) * K + k0 + c]);
        }
#pragma unroll
        for (int i = 0; i < 4; i++) {
            int p = tid + i * 256, r = p >> 4, c = (p & 15) * 8;
            cpa16(su32(&Bs[s][r * D_BLD + c]), &W[(size_t)(k0 + r) * N + n0 + c]);
        }
        cp_commit();
    };

    const int nk = K / 64;
    load_tile(0, 0);
    for (int kt = 0; kt < nk; kt++) {
        int s = kt & 1;
        if (kt + 1 < nk) {
            load_tile(s ^ 1, (kt + 1) * 64);
            asm volatile("cp.async.wait_group 1;");
        } else {
            asm volatile("cp.async.wait_group 0;");
        }
        __syncthreads();
#pragma unroll
        for (int kk = 0; kk < 64; kk += 16) {
            HFragA fa[4]; HFragB fb[2];
#pragma unroll
            for (int i = 0; i < 4; i++)
                wmma::load_matrix_sync(fa[i], &As[s][(wm * 64 + i * 16) * D_ALD + kk], D_ALD);
#pragma unroll
            for (int j = 0; j < 2; j++)
                wmma::load_matrix_sync(fb[j], &Bs[s][kk * D_BLD + wn * 32 + j * 16], D_BLD);
#pragma unroll
            for (int i = 0; i < 4; i++)
#pragma unroll
                for (int j = 0; j < 2; j++) wmma::mma_sync(acc[i][j], fa[i], fb[j], acc[i][j]);
        }
        __syncthreads();
    }
    float* Cs = (float*)smraw;
#pragma unroll
    for (int i = 0; i < 4; i++)
#pragma unroll
        for (int j = 0; j < 2; j++)
            wmma::store_matrix_sync(&Cs[(wm * 64 + i * 16) * D_CLD + wn * 32 + j * 16],
                                    acc[i][j], D_CLD, wmma::mem_row_major);
    __syncthreads();
#pragma unroll
    for (int i = 0; i < 16; i++) {
        int p = tid + i * 256, r = p >> 5, c = (p & 31) * 4;
        float4 v = *(float4*)&Cs[r * D_CLD + c];
        int gc = n0 + c;
        float4 bv = *(const float4*)&bias[gc];
        v.x += bv.x; v.y += bv.y; v.z += bv.z; v.w += bv.w;
        size_t off = (size_t)(m0 + r) * N + gc;
        if (resid) {
            float4 rv = *(const float4*)&resid[off];
            v.x += rv.x; v.y += rv.y; v.z += rv.z; v.w += rv.w;
        }
        if (flags & 1) {
            v.x = fmaxf(v.x, 0.f); v.y = fmaxf(v.y, 0.f);
            v.z = fmaxf(v.z, 0.f); v.w = fmaxf(v.w, 0.f);
        }
        if (flags & 2) {
            *(__half2*)&Ch[off]     = __floats2half2_rn(v.x, v.y);
            *(__half2*)&Ch[off + 2] = __floats2half2_rn(v.z, v.w);
        } else {
            *(float4*)&Cf[off] = v;
        }
    }
}

// ===== fused attention: per CTA 128 q-rows x one head; two-pass softmax, all on-chip =====
#define FA_QS 0                      /* 128 x 72 halves = 18432 */
#define FA_KS 18432                  /* 2 x (64 x 72 halves)    = 18432 */
#define FA_VS 36864                  /* 2 x (64 x 72 halves)    = 18432 */
#define FA_SS 55296                  /* 128 x 68 fp32           = 34816 */
#define FA_PS 90112                  /* 128 x 72 halves         = 18432 */
#define FA_MS 108544                 /* 128 fp32 = 512 */
#define FA_LS 109056                 /* 128 fp32 = 512 */
#define FA_SMEM 109568

__global__ __launch_bounds__(256) void fattn_kernel(
    const __half* __restrict__ Q, const __half* __restrict__ Kg,
    const __half* __restrict__ Vg, __half* __restrict__ O, int kv_tokens) {
    const float alpha = 0.125f;
    int z = blockIdx.y, bi = z / HEADS, hi = z % HEADS;
    int m0 = blockIdx.x * 128;
    const __half* Qb = Q  + ((size_t)bi * SP + m0) * D_MODEL + hi * D_HEAD;
    const __half* Kb = Kg + (size_t)bi * kv_tokens * D_MODEL + hi * D_HEAD;
    const __half* Vb = Vg + (size_t)bi * kv_tokens * D_MODEL + hi * D_HEAD;
    __half* Ob = O + ((size_t)bi * SP + m0) * D_MODEL + hi * D_HEAD;

    __half* Qs = (__half*)(smraw + FA_QS);
    __half* Ks = (__half*)(smraw + FA_KS);
    __half* Vs = (__half*)(smraw + FA_VS);
    float*  Ss = (float*)(smraw + FA_SS);
    __half* Ps = (__half*)(smraw + FA_PS);
    float*  Ms = (float*)(smraw + FA_MS);
    float*  Ls = (float*)(smraw + FA_LS);

    int tid = threadIdx.x;
    int warp = tid >> 5, wm = warp & 3, wn = warp >> 2;   // 4x2: warp tile 32x32 on 128x64

    // load Q tile (1024 chunks of 16B = 128x64 halves)
#pragma unroll
    for (int i = 0; i < 4; i++) {
        int p = tid + i * 256, r = p >> 3, c = (p & 7) * 8;
        cpa16(su32(&Qs[r * 72 + c]), &Qb[(size_t)r * D_MODEL + c]);
    }
    cp_commit();
    if (tid < 128) { Ms[tid] = -1e30f; Ls[tid] = 0.f; }
    asm volatile("cp.async.wait_group 0;");
    __syncthreads();

    const int nt = kv_tokens / 64;

    auto load_k = [&](int t, int s) {
#pragma unroll
        for (int i = 0; i < 2; i++) {
            int p = tid + i * 256, r = p >> 3, c = (p & 7) * 8;
            cpa16(su32(&Ks[s * 4608 + r * 72 + c]), &Kb[(size_t)(t * 64 + r) * D_MODEL + c]);
        }
    };
    auto load_v = [&](int t, int s) {
#pragma unroll
        for (int i = 0; i < 2; i++) {
            int p = tid + i * 256, r = p >> 3, c = (p & 7) * 8;
            cpa16(su32(&Vs[s * 4608 + r * 72 + c]), &Vb[(size_t)(t * 64 + r) * D_MODEL + c]);
        }
    };
    auto s_mma_store = [&](int s) {
        HFragC sacc[2][2];
#pragma unroll
        for (int i = 0; i < 2; i++)
#pragma unroll
            for (int j = 0; j < 2; j++) wmma::fill_fragment(sacc[i][j], 0.f);
#pragma unroll
        for (int kk = 0; kk < 64; kk += 16) {
            HFragA fa[2]; HFragBT fb[2];
#pragma unroll
            for (int i = 0; i < 2; i++)
                wmma::load_matrix_sync(fa[i], &Qs[(wm * 32 + i * 16) * 72 + kk], 72);
#pragma unroll
            for (int j = 0; j < 2; j++)
                wmma::load_matrix_sync(fb[j], &Ks[s * 4608 + (wn * 32 + j * 16) * 72 + kk], 72);
#pragma unroll
            for (int i = 0; i < 2; i++)
#pragma unroll
                for (int j = 0; j < 2; j++) wmma::mma_sync(sacc[i][j], fa[i], fb[j], sacc[i][j]);
        }
#pragma unroll
        for (int i = 0; i < 2; i++)
#pragma unroll
            for (int j = 0; j < 2; j++)
                wmma::store_matrix_sync(&Ss[(wm * 32 + i * 16) * 68 + wn * 32 + j * 16],
                                        sacc[i][j], 68, wmma::mem_row_major);
    };

    // ---------- PASS 1: row stats ----------
    load_k(0, 0); cp_commit();
    for (int t = 0; t < nt; t++) {
        int s = t & 1;
        asm volatile("cp.async.wait_group 0;");
        __syncthreads();
        s_mma_store(s);
        if (t + 1 < nt) { load_k(t + 1, s ^ 1); cp_commit(); }
        __syncthreads();
        if (tid < 128) {
            int r = tid;
            float m_old = Ms[r], l_old = Ls[r];
            const float* Sr = Ss + r * 68;
            float tm = -1e30f;
#pragma unroll
            for (int j = 0; j < 64; j++) tm = fmaxf(tm, Sr[j]);
            tm *= alpha;
            float m_new = fmaxf(m_old, tm);
            float sum = 0.f;
#pragma unroll
            for (int j = 0; j < 64; j++) sum += expf(Sr[j] * alpha - m_new);
            Ls[r] = l_old * expf(m_old - m_new) + sum;
            Ms[r] = m_new;
        }
        __syncthreads();
    }
    if (tid < 128) Ls[tid] = 1.f / Ls[tid];
    __syncthreads();

    // ---------- PASS 2: P = exp(s-m)/l ; O += P@V ----------
    HFragC oacc[2][2];
#pragma unroll
    for (int i = 0; i < 2; i++)
#pragma unroll
        for (int j = 0; j < 2; j++) wmma::fill_fragment(oacc[i][j], 0.f);

    load_k(0, 0); load_v(0, 0); cp_commit();
    for (int t = 0; t < nt; t++) {
        int s = t & 1;
        asm volatile("cp.async.wait_group 0;");
        __syncthreads();
        s_mma_store(s);
        if (t + 1 < nt) { load_k(t + 1, s ^ 1); load_v(t + 1, s ^ 1); cp_commit(); }
        __syncthreads();
        // P tile fp16  (256 threads x 32 halves = 8192 = 128x64)
        {
            int r = tid >> 1, cb = (tid & 1) * 32;
            float m = Ms[r], li = Ls[r];
            const float* Sr = Ss + r * 68 + cb;
            __half* Pr = Ps + r * 72 + cb;
#pragma unroll
            for (int j = 0; j < 32; j += 2) {
                float a = expf(Sr[j] * alpha - m) * li;
                float b = expf(Sr[j + 1] * alpha - m) * li;
                *(__half2*)&Pr[j] = __floats2half2_rn(a, b);
            }
        }
        __syncthreads();
        // O += P @ V
#pragma unroll
        for (int kk = 0; kk < 64; kk += 16) {
            HFragA fa[2]; HFragB fb[2];
#pragma unroll
            for (int i = 0; i < 2; i++)
                wmma::load_matrix_sync(fa[i], &Ps[(wm * 32 + i * 16) * 72 + kk], 72);
#pragma unroll
            for (int j = 0; j < 2; j++)
                wmma::load_matrix_sync(fb[j], &Vs[s * 4608 + kk * 72 + wn * 32 + j * 16], 72);
#pragma unroll
            for (int i = 0; i < 2; i++)
#pragma unroll
                for (int j = 0; j < 2; j++) wmma::mma_sync(oacc[i][j], fa[i], fb[j], oacc[i][j]);
        }
        __syncthreads();
    }
    // write O (128 x 64 = 4096 half2 units -> 16 iterations of 256 threads)
#pragma unroll
    for (int i = 0; i < 2; i++)
#pragma unroll
        for (int j = 0; j < 2; j++)
            wmma::store_matrix_sync(&Ss[(wm * 32 + i * 16) * 68 + wn * 32 + j * 16],
                                    oacc[i][j], 68, wmma::mem_row_major);
    __syncthreads();
#pragma unroll
    for (int i = 0; i < 16; i++) {
        int p = tid + i * 256;          // 4096 half2 units
        int r = p >> 5, c2 = (p & 31) * 2;
        float a = Ss[r * 68 + c2], b = Ss[r * 68 + c2 + 1];
        *(__half2*)&Ob[(size_t)r * D_MODEL + c2] = __floats2half2_rn(a, b);
    }
}

// ---------------- launcher ----------------
extern "C" void kernel_launch(void* const* d_in, const int* in_sizes, int n_in,
                              void* d_out, int out_size) {
    (void)in_sizes; (void)n_in; (void)out_size;
    const float* image  = (const float*)d_in[0];
    const float* prompt = (const float*)d_in[1];
    const float* posi   = (const float*)d_in[2];
    const float* posp   = (const float*)d_in[3];
    const float* ln1g = (const float*)d_in[4],  *ln1b = (const float*)d_in[5];
    const float* ln2g = (const float*)d_in[6],  *ln2b = (const float*)d_in[7];
    const float* ln3g = (const float*)d_in[8],  *ln3b = (const float*)d_in[9];
    const float* lnig = (const float*)d_in[10], *lnib = (const float*)d_in[11];
    const float* pp_wq = (const float*)d_in[12], *pp_bq = (const float*)d_in[13];
    const float* pp_wk = (const float*)d_in[14], *pp_bk = (const float*)d_in[15];
    const float* pp_wv = (const float*)d_in[16], *pp_bv = (const float*)d_in[17];
    const float* pp_wo = (const float*)d_in[18], *pp_bo = (const float*)d_in[19];
    const float* pi_wq = (const float*)d_in[20], *pi_bq = (const float*)d_in[21];
    const float* pi_wk = (const float*)d_in[22], *pi_bk = (const float*)d_in[23];
    const float* pi_wv = (const float*)d_in[24], *pi_bv = (const float*)d_in[25];
    const float* pi_wo = (const float*)d_in[26], *pi_bo = (const float*)d_in[27];
    const float* ff_w1 = (const float*)d_in[28], *ff_b1 = (const float*)d_in[29];
    const float* ff_w2 = (const float*)d_in[30], *ff_b2 = (const float*)d_in[31];
    float* out = (float*)d_out;

    float *prompt0, *p1, *p2;
    __half *x, *xi, *q, *k, *v, *attn, *h, *wh;
    cudaGetSymbolAddress((void**)&prompt0, g_prompt0);
    cudaGetSymbolAddress((void**)&p1,    g_p1);
    cudaGetSymbolAddress((void**)&p2,    g_p2);
    cudaGetSymbolAddress((void**)&x,     g_x);
    cudaGetSymbolAddress((void**)&xi,    g_xi);
    cudaGetSymbolAddress((void**)&q,     g_q);
    cudaGetSymbolAddress((void**)&k,     g_k);
    cudaGetSymbolAddress((void**)&v,     g_v);
    cudaGetSymbolAddress((void**)&attn,  g_attn);
    cudaGetSymbolAddress((void**)&h,     g_h);
    cudaGetSymbolAddress((void**)&wh,    g_wh);

    __half* W[10];
    const float* srcw[10] = {pp_wq, pp_wk, pp_wv, pp_wo, pi_wq, pi_wk, pi_wv, pi_wo, ff_w1, ff_w2};
    for (int i = 0; i < 10; i++) W[i] = wh + (size_t)i * WELEM;

    cudaFuncSetAttribute(dense_gemm_kernel, cudaFuncAttributeMaxDynamicSharedMemorySize, DENSE_SMEM);
    cudaFuncSetAttribute(fattn_kernel,      cudaFuncAttributeMaxDynamicSharedMemorySize, FA_SMEM);

    // 0. all weights -> fp16, one launch
    {
        WSrc S; for (int i = 0; i < 10; i++) S.p[i] = srcw[i];
        half_w_all_kernel<<<dim3(WELEM / 4 / 256, 10), 256>>>(S, wh);
    }
    // 1. prompt0 = prompt + posp
    add4_kernel<<<(TOKP * D_MODEL / 4 + 255) / 256, 256>>>(
        (const float4*)prompt, (const float4*)posp, (float4*)prompt0, TOKP * D_MODEL / 4);
    // 2. x = LN(prompt0) -> fp16
    addln_kernel<<<TOKP, 256>>>(prompt0, nullptr, ln1g, ln1b, x);
    // 3. self QKV fused (z=3) -> fp16
    {
        DZ P = {{W[0], W[1], W[2]}, {pp_bq, pp_bk, pp_bv}, {nullptr, nullptr, nullptr},
                {nullptr, nullptr, nullptr}, {q, k, v}, {2, 2, 2}};
        dense_gemm_kernel<<<dim3(6, 32, 3), 256, DENSE_SMEM>>>(x, P, TOKP);
    }
    // 4. fused self-attention -> attn (fp16)
    fattn_kernel<<<dim3(SP / 128, NB * HEADS), 256, FA_SMEM>>>(q, k, v, attn, SP);
    // 5. p1 = attn @ Wo + bo + prompt (fp32)
    {
        DZ P = {{W[3], nullptr, nullptr}, {pp_bo, nullptr, nullptr}, {prompt, nullptr, nullptr},
                {p1, nullptr, nullptr}, {nullptr, nullptr, nullptr}, {0, 0, 0}};
        dense_gemm_kernel<<<dim3(6, 32, 1), 256, DENSE_SMEM>>>(attn, P, TOKP);
    }
    // 6. x = LN(p1 + prompt0) -> fp16
    addln_kernel<<<TOKP, 256>>>(p1, prompt0, ln2g, ln2b, x);
    // 7. xi = LN(image + posi) -> fp16
    addln_kernel<<<TOKI, 256>>>(image, posi, lnig, lnib, xi);
    // 8. cross Q -> fp16
    {
        DZ P = {{W[4], nullptr, nullptr}, {pi_bq, nullptr, nullptr}, {nullptr, nullptr, nullptr},
                {nullptr, nullptr, nullptr}, {q, nullptr, nullptr}, {2, 0, 0}};
        dense_gemm_kernel<<<dim3(6, 32, 1), 256, DENSE_SMEM>>>(x, P, TOKP);
    }
    // 9. image K,V fused (z=2) -> fp16
    {
        DZ P = {{W[5], W[6], nullptr}, {pi_bk, pi_bv, nullptr}, {nullptr, nullptr, nullptr},
                {nullptr, nullptr, nullptr}, {k, v, nullptr}, {2, 2, 0}};
        dense_gemm_kernel<<<dim3(6, 128, 2), 256, DENSE_SMEM>>>(xi, P, TOKI);
    }
    // 10. fused cross-attention -> attn (fp16)
    fattn_kernel<<<dim3(SP / 128, NB * HEADS), 256, FA_SMEM>>>(q, k, v, attn, SI);
    // 11. p2 = attn @ Wo + bo + p1 (fp32)
    {
        DZ P = {{W[7], nullptr, nullptr}, {pi_bo, nullptr, nullptr}, {p1, nullptr, nullptr},
                {p2, nullptr, nullptr}, {nullptr, nullptr, nullptr}, {0, 0, 0}};
        dense_gemm_kernel<<<dim3(6, 32, 1), 256, DENSE_SMEM>>>(attn, P, TOKP);
    }
    // 12. x = LN(p2 + prompt0) -> fp16
    addln_kernel<<<TOKP, 256>>>(p2, prompt0, ln3g, ln3b, x);
    // 13. h = relu(x @ W1 + b1) -> fp16
    {
        DZ P = {{W[8], nullptr, nullptr}, {ff_b1, nullptr, nullptr}, {nullptr, nullptr, nullptr},
                {nullptr, nullptr, nullptr}, {h, nullptr, nullptr}, {3, 0, 0}};
        dense_gemm_kernel<<<dim3(6, 32, 1), 256, DENSE_SMEM>>>(x, P, TOKP);
    }
    // 14. out = h @ W2 + b2 (fp32 final)
    {
        DZ P = {{W[9], nullptr, nullptr}, {ff_b2, nullptr, nullptr}, {nullptr, nullptr, nullptr},
                {out, nullptr, nullptr}, {nullptr, nullptr, nullptr}, {0, 0, 0}};
        dense_gemm_kernel<<<dim3(6, 32, 1), 256, DENSE_SMEM>>>(h, P, TOKP);
    }
}

// round 12
// speedup vs baseline: 3.5963x; 1.1340x over previous
#include <cuda_runtime.h>
#include <cuda_fp16.h>
#include <mma.h>
#include <cstdint>

using namespace nvcuda;

#define D_MODEL 768
#define HEADS   12
#define D_HEAD  64
#define NB      16
#define SP      256
#define SI      1024
#define TOKP    (NB*SP)     /* 4096  */
#define TOKI    (NB*SI)     /* 16384 */
#define WELEM   (D_MODEL*D_MODEL)

// ---------------- scratch (device globals: no allocations allowed) ----------------
__device__ float  g_prompt0[TOKP*D_MODEL];
__device__ float  g_p1     [TOKP*D_MODEL];
__device__ float  g_p2     [TOKP*D_MODEL];
__device__ __half g_x   [TOKP*D_MODEL];
__device__ __half g_xi  [TOKI*D_MODEL];
__device__ __half g_q   [TOKP*D_MODEL];
__device__ __half g_k   [TOKI*D_MODEL];
__device__ __half g_v   [TOKI*D_MODEL];
__device__ __half g_attn[TOKP*D_MODEL];
__device__ __half g_h   [TOKP*D_MODEL];
__device__ __half g_wh  [10][WELEM];   /* fp16 weights, [k][n] layout */

// ---------------- helpers ----------------
__device__ __forceinline__ void cpa16(uint32_t sa, const void* g) {
    asm volatile("cp.async.cg.shared.global [%0], [%1], 16;" :: "r"(sa), "l"(g));
}
__device__ __forceinline__ void cp_commit() { asm volatile("cp.async.commit_group;"); }
__device__ __forceinline__ uint32_t su32(const void* p) {
    return (uint32_t)__cvta_generic_to_shared(p);
}

// ---------------- fused weight fp32 -> fp16 (all 10 matrices, one launch) ----------------
struct WSrc { const float* p[10]; };
__global__ void half_w_all_kernel(WSrc S, __half* __restrict__ dst) {
    int mat = blockIdx.y;
    int i = blockIdx.x * blockDim.x + threadIdx.x;
    const float4* s = (const float4*)S.p[mat];
    float4 v = s[i];
    __half* d = dst + (size_t)mat * WELEM + (size_t)i * 4;
    *(__half2*)&d[0] = __floats2half2_rn(v.x, v.y);
    *(__half2*)&d[2] = __floats2half2_rn(v.z, v.w);
}

// ---------------- elementwise add (float4) ----------------
__global__ void add4_kernel(const float4* __restrict__ a, const float4* __restrict__ b,
                            float4* __restrict__ o, int n4) {
    int i = blockIdx.x * blockDim.x + threadIdx.x;
    if (i < n4) {
        float4 x = a[i], y = b[i];
        x.x += y.x; x.y += y.y; x.z += y.z; x.w += y.w;
        o[i] = x;
    }
}

// ---------------- (optional add) + layernorm -> fp16 ----------------
__global__ void addln_kernel(const float* __restrict__ a, const float* __restrict__ b,
                             const float* __restrict__ g, const float* __restrict__ be,
                             __half* __restrict__ o) {
    int row = blockIdx.x;
    const float* pa = a + (size_t)row * D_MODEL;
    const float* pb = b ? b + (size_t)row * D_MODEL : nullptr;
    float x[3];
    float s = 0.f, sq = 0.f;
#pragma unroll
    for (int j = 0; j < 3; j++) {
        int i = threadIdx.x + j * 256;
        float v = pa[i];
        if (pb) v += pb[i];
        x[j] = v; s += v; sq += v * v;
    }
    __shared__ float sb[16];
    unsigned wid = threadIdx.x >> 5, lane = threadIdx.x & 31;
#pragma unroll
    for (int off = 16; off; off >>= 1) {
        s  += __shfl_xor_sync(0xffffffffu, s,  off);
        sq += __shfl_xor_sync(0xffffffffu, sq, off);
    }
    if (lane == 0) { sb[wid] = s; sb[8 + wid] = sq; }
    __syncthreads();
    if (threadIdx.x < 32) {
        float s2 = (lane < 8) ? sb[lane] : 0.f;
        float q2 = (lane < 8) ? sb[8 + lane] : 0.f;
#pragma unroll
        for (int off = 4; off; off >>= 1) {
            s2 += __shfl_xor_sync(0xffffffffu, s2, off);
            q2 += __shfl_xor_sync(0xffffffffu, q2, off);
        }
        if (lane == 0) { sb[0] = s2; sb[1] = q2; }
    }
    __syncthreads();
    float mean = sb[0] * (1.f / 768.f);
    float var  = sb[1] * (1.f / 768.f) - mean * mean;
    float rs   = rsqrtf(var + 1e-5f);
#pragma unroll
    for (int j = 0; j < 3; j++) {
        int i = threadIdx.x + j * 256;
        o[(size_t)row * D_MODEL + i] = __float2half_rn((x[j] - mean) * rs * g[i] + be[i]);
    }
}

// ---------------- wmma fp16 typedefs ----------------
using HFragA  = wmma::fragment<wmma::matrix_a, 16, 16, 16, __half, wmma::row_major>;
using HFragB  = wmma::fragment<wmma::matrix_b, 16, 16, 16, __half, wmma::row_major>;
using HFragBT = wmma::fragment<wmma::matrix_b, 16, 16, 16, __half, wmma::col_major>;
using HFragC  = wmma::fragment<wmma::accumulator, 16, 16, 16, float>;

extern __shared__ __align__(16) char smraw[];

// ===== dense GEMM: 128x128xK64 fp16, warp 64x32, cp.async 3-stage, 1 sync/iter =====
struct DZ {
    const __half* W[3];
    const float*  Bi[3];
    const float*  R[3];
    float*  Cf[3];
    __half* Ch[3];
    int fl[3];
};

#define D_ALD 72
#define D_BLD 136
#define D_ASZ (128 * D_ALD)
#define D_BSZ (64 * D_BLD)
#define D_STG (D_ASZ + D_BSZ)        /* 17920 halves = 35840 B */
#define D_CLD 132
#define DENSE_SMEM (3 * D_STG * 2)   /* 107520 B; 2 CTAs = 215KB fits */

__global__ __launch_bounds__(256, 2) void dense_gemm_kernel(
    const __half* __restrict__ A, DZ P, int M) {
    constexpr int K = D_MODEL, N = D_MODEL;
    const __half* W    = P.W[blockIdx.z];
    const float* bias  = P.Bi[blockIdx.z];
    const float* resid = P.R[blockIdx.z];
    float*  Cf         = P.Cf[blockIdx.z];
    __half* Ch         = P.Ch[blockIdx.z];
    int flags          = P.fl[blockIdx.z];

    __half* sm = (__half*)smraw;
    int tid = threadIdx.x;
    int m0 = blockIdx.y * 128, n0 = blockIdx.x * 128;
    int warp = tid >> 5, wm = warp & 1, wn = warp >> 1;

    HFragC acc[4][2];
#pragma unroll
    for (int i = 0; i < 4; i++)
#pragma unroll
        for (int j = 0; j < 2; j++) wmma::fill_fragment(acc[i][j], 0.f);

    auto load_tile = [&](int s, int k0) {
        __half* As = sm + s * D_STG;
        __half* Bs = As + D_ASZ;
#pragma unroll
        for (int i = 0; i < 4; i++) {
            int p = tid + i * 256, r = p >> 3, c = (p & 7) * 8;
            cpa16(su32(&As[r * D_ALD + c]), &A[(size_t)(m0 + r) * K + k0 + c]);
        }
#pragma unroll
        for (int i = 0; i < 4; i++) {
            int p = tid + i * 256, r = p >> 4, c = (p & 15) * 8;
            cpa16(su32(&Bs[r * D_BLD + c]), &W[(size_t)(k0 + r) * N + n0 + c]);
        }
        cp_commit();
    };

    const int nk = K / 64;   // 12
    load_tile(0, 0);
    load_tile(1, 64);
    for (int kt = 0; kt < nk; kt++) {
        int s = kt % 3;
        if (kt + 1 < nk) asm volatile("cp.async.wait_group 1;");
        else             asm volatile("cp.async.wait_group 0;");
        __syncthreads();            // tile kt ready AND all warps done with kt-1
        if (kt + 2 < nk) load_tile((kt + 2) % 3, (kt + 2) * 64);
        __half* As = sm + s * D_STG;
        __half* Bs = As + D_ASZ;
#pragma unroll
        for (int kk = 0; kk < 64; kk += 16) {
            HFragA fa[4]; HFragB fb[2];
#pragma unroll
            for (int i = 0; i < 4; i++)
                wmma::load_matrix_sync(fa[i], &As[(wm * 64 + i * 16) * D_ALD + kk], D_ALD);
#pragma unroll
            for (int j = 0; j < 2; j++)
                wmma::load_matrix_sync(fb[j], &Bs[kk * D_BLD + wn * 32 + j * 16], D_BLD);
#pragma unroll
            for (int i = 0; i < 4; i++)
#pragma unroll
                for (int j = 0; j < 2; j++) wmma::mma_sync(acc[i][j], fa[i], fb[j], acc[i][j]);
        }
    }
    __syncthreads();
    float* Cs = (float*)smraw;
#pragma unroll
    for (int i = 0; i < 4; i++)
#pragma unroll
        for (int j = 0; j < 2; j++)
            wmma::store_matrix_sync(&Cs[(wm * 64 + i * 16) * D_CLD + wn * 32 + j * 16],
                                    acc[i][j], D_CLD, wmma::mem_row_major);
    __syncthreads();
#pragma unroll
    for (int i = 0; i < 16; i++) {
        int p = tid + i * 256, r = p >> 5, c = (p & 31) * 4;
        float4 v = *(float4*)&Cs[r * D_CLD + c];
        int gc = n0 + c;
        float4 bv = *(const float4*)&bias[gc];
        v.x += bv.x; v.y += bv.y; v.z += bv.z; v.w += bv.w;
        size_t off = (size_t)(m0 + r) * N + gc;
        if (resid) {
            float4 rv = *(const float4*)&resid[off];
            v.x += rv.x; v.y += rv.y; v.z += rv.z; v.w += rv.w;
        }
        if (flags & 1) {
            v.x = fmaxf(v.x, 0.f); v.y = fmaxf(v.y, 0.f);
            v.z = fmaxf(v.z, 0.f); v.w = fmaxf(v.w, 0.f);
        }
        if (flags & 2) {
            *(__half2*)&Ch[off]     = __floats2half2_rn(v.x, v.y);
            *(__half2*)&Ch[off + 2] = __floats2half2_rn(v.z, v.w);
        } else {
            *(float4*)&Cf[off] = v;
        }
    }
}

// ===== fused attention: 128 q-rows x one head per CTA; two-pass softmax, 2 CTAs/SM =====
#define FA_QS 0                      /* 128 x 72 halves = 18432 */
#define FA_KS 18432                  /* 2 x (64 x 72 halves)    = 18432 */
#define FA_VS 36864                  /* 2 x (64 x 72 halves)    = 18432 */
#define FA_SS 55296                  /* 128 x 68 fp32           = 34816 */
#define FA_PS 90112                  /* 128 x 72 halves         = 18432 */
#define FA_MS 108544                 /* 128 fp32 = 512 */
#define FA_LS 109056                 /* 128 fp32 = 512 */
#define FA_SMEM 109568               /* x2 CTAs = 219KB fits */

__global__ __launch_bounds__(256, 2) void fattn_kernel(
    const __half* __restrict__ Q, const __half* __restrict__ Kg,
    const __half* __restrict__ Vg, __half* __restrict__ O, int kv_tokens) {
    const float alpha = 0.125f;
    int z = blockIdx.y, bi = z / HEADS, hi = z % HEADS;
    int m0 = blockIdx.x * 128;
    const __half* Qb = Q  + ((size_t)bi * SP + m0) * D_MODEL + hi * D_HEAD;
    const __half* Kb = Kg + (size_t)bi * kv_tokens * D_MODEL + hi * D_HEAD;
    const __half* Vb = Vg + (size_t)bi * kv_tokens * D_MODEL + hi * D_HEAD;
    __half* Ob = O + ((size_t)bi * SP + m0) * D_MODEL + hi * D_HEAD;

    __half* Qs = (__half*)(smraw + FA_QS);
    __half* Ks = (__half*)(smraw + FA_KS);
    __half* Vs = (__half*)(smraw + FA_VS);
    float*  Ss = (float*)(smraw + FA_SS);
    __half* Ps = (__half*)(smraw + FA_PS);
    float*  Ms = (float*)(smraw + FA_MS);
    float*  Ls = (float*)(smraw + FA_LS);

    int tid = threadIdx.x;
    int warp = tid >> 5, wm = warp & 3, wn = warp >> 2;

#pragma unroll
    for (int i = 0; i < 4; i++) {
        int p = tid + i * 256, r = p >> 3, c = (p & 7) * 8;
        cpa16(su32(&Qs[r * 72 + c]), &Qb[(size_t)r * D_MODEL + c]);
    }
    cp_commit();
    if (tid < 128) { Ms[tid] = -1e30f; Ls[tid] = 0.f; }
    asm volatile("cp.async.wait_group 0;");
    __syncthreads();

    const int nt = kv_tokens / 64;

    auto load_k = [&](int t, int s) {
#pragma unroll
        for (int i = 0; i < 2; i++) {
            int p = tid + i * 256, r = p >> 3, c = (p & 7) * 8;
            cpa16(su32(&Ks[s * 4608 + r * 72 + c]), &Kb[(size_t)(t * 64 + r) * D_MODEL + c]);
        }
    };
    auto load_v = [&](int t, int s) {
#pragma unroll
        for (int i = 0; i < 2; i++) {
            int p = tid + i * 256, r = p >> 3, c = (p & 7) * 8;
            cpa16(su32(&Vs[s * 4608 + r * 72 + c]), &Vb[(size_t)(t * 64 + r) * D_MODEL + c]);
        }
    };
    auto s_mma_store = [&](int s) {
        HFragC sacc[2][2];
#pragma unroll
        for (int i = 0; i < 2; i++)
#pragma unroll
            for (int j = 0; j < 2; j++) wmma::fill_fragment(sacc[i][j], 0.f);
#pragma unroll
        for (int kk = 0; kk < 64; kk += 16) {
            HFragA fa[2]; HFragBT fb[2];
#pragma unroll
            for (int i = 0; i < 2; i++)
                wmma::load_matrix_sync(fa[i], &Qs[(wm * 32 + i * 16) * 72 + kk], 72);
#pragma unroll
            for (int j = 0; j < 2; j++)
                wmma::load_matrix_sync(fb[j], &Ks[s * 4608 + (wn * 32 + j * 16) * 72 + kk], 72);
#pragma unroll
            for (int i = 0; i < 2; i++)
#pragma unroll
                for (int j = 0; j < 2; j++) wmma::mma_sync(sacc[i][j], fa[i], fb[j], sacc[i][j]);
        }
#pragma unroll
        for (int i = 0; i < 2; i++)
#pragma unroll
            for (int j = 0; j < 2; j++)
                wmma::store_matrix_sync(&Ss[(wm * 32 + i * 16) * 68 + wn * 32 + j * 16],
                                        sacc[i][j], 68, wmma::mem_row_major);
    };

    // ---------- PASS 1: row stats (2 threads/row, shfl-combined) ----------
    load_k(0, 0); cp_commit();
    for (int t = 0; t < nt; t++) {
        int s = t & 1;
        asm volatile("cp.async.wait_group 0;");
        __syncthreads();
        s_mma_store(s);
        if (t + 1 < nt) { load_k(t + 1, s ^ 1); cp_commit(); }
        __syncthreads();
        {
            int r = tid >> 1, hf = tid & 1;
            const float* Sr = Ss + r * 68 + hf * 32;
            float m_old = Ms[r], l_old = Ls[r];
            float tm = -1e30f;
#pragma unroll
            for (int j = 0; j < 32; j++) tm = fmaxf(tm, Sr[j]);
            tm *= alpha;
            float tmo = __shfl_xor_sync(0xffffffffu, tm, 1);
            float m_new = fmaxf(fmaxf(tm, tmo), m_old);
            float sum = 0.f;
#pragma unroll
            for (int j = 0; j < 32; j++) sum += expf(Sr[j] * alpha - m_new);
            sum += __shfl_xor_sync(0xffffffffu, sum, 1);
            if (hf == 0) {
                Ls[r] = l_old * expf(m_old - m_new) + sum;
                Ms[r] = m_new;
            }
        }
        __syncthreads();
    }
    if (tid < 128) Ls[tid] = 1.f / Ls[tid];
    __syncthreads();

    // ---------- PASS 2: P = exp(s-m)/l ; O += P@V ----------
    HFragC oacc[2][2];
#pragma unroll
    for (int i = 0; i < 2; i++)
#pragma unroll
        for (int j = 0; j < 2; j++) wmma::fill_fragment(oacc[i][j], 0.f);

    load_k(0, 0); load_v(0, 0); cp_commit();
    for (int t = 0; t < nt; t++) {
        int s = t & 1;
        asm volatile("cp.async.wait_group 0;");
        __syncthreads();
        s_mma_store(s);
        if (t + 1 < nt) { load_k(t + 1, s ^ 1); load_v(t + 1, s ^ 1); cp_commit(); }
        __syncthreads();
        {
            int r = tid >> 1, cb = (tid & 1) * 32;
            float m = Ms[r], li = Ls[r];
            const float* Sr = Ss + r * 68 + cb;
            __half* Pr = Ps + r * 72 + cb;
#pragma unroll
            for (int j = 0; j < 32; j += 2) {
                float a = expf(Sr[j] * alpha - m) * li;
                float b = expf(Sr[j + 1] * alpha - m) * li;
                *(__half2*)&Pr[j] = __floats2half2_rn(a, b);
            }
        }
        __syncthreads();
#pragma unroll
        for (int kk = 0; kk < 64; kk += 16) {
            HFragA fa[2]; HFragB fb[2];
#pragma unroll
            for (int i = 0; i < 2; i++)
                wmma::load_matrix_sync(fa[i], &Ps[(wm * 32 + i * 16) * 72 + kk], 72);
#pragma unroll
            for (int j = 0; j < 2; j++)
                wmma::load_matrix_sync(fb[j], &Vs[s * 4608 + kk * 72 + wn * 32 + j * 16], 72);
#pragma unroll
            for (int i = 0; i < 2; i++)
#pragma unroll
                for (int j = 0; j < 2; j++) wmma::mma_sync(oacc[i][j], fa[i], fb[j], oacc[i][j]);
        }
        __syncthreads();
    }
#pragma unroll
    for (int i = 0; i < 2; i++)
#pragma unroll
        for (int j = 0; j < 2; j++)
            wmma::store_matrix_sync(&Ss[(wm * 32 + i * 16) * 68 + wn * 32 + j * 16],
                                    oacc[i][j], 68, wmma::mem_row_major);
    __syncthreads();
#pragma unroll
    for (int i = 0; i < 16; i++) {
        int p = tid + i * 256;          // 4096 half2 units = 128x64
        int r = p >> 5, c2 = (p & 31) * 2;
        float a = Ss[r * 68 + c2], b = Ss[r * 68 + c2 + 1];
        *(__half2*)&Ob[(size_t)r * D_MODEL + c2] = __floats2half2_rn(a, b);
    }
}

// ---------------- launcher ----------------
extern "C" void kernel_launch(void* const* d_in, const int* in_sizes, int n_in,
                              void* d_out, int out_size) {
    (void)in_sizes; (void)n_in; (void)out_size;
    const float* image  = (const float*)d_in[0];
    const float* prompt = (const float*)d_in[1];
    const float* posi   = (const float*)d_in[2];
    const float* posp   = (const float*)d_in[3];
    const float* ln1g = (const float*)d_in[4],  *ln1b = (const float*)d_in[5];
    const float* ln2g = (const float*)d_in[6],  *ln2b = (const float*)d_in[7];
    const float* ln3g = (const float*)d_in[8],  *ln3b = (const float*)d_in[9];
    const float* lnig = (const float*)d_in[10], *lnib = (const float*)d_in[11];
    const float* pp_wq = (const float*)d_in[12], *pp_bq = (const float*)d_in[13];
    const float* pp_wk = (const float*)d_in[14], *pp_bk = (const float*)d_in[15];
    const float* pp_wv = (const float*)d_in[16], *pp_bv = (const float*)d_in[17];
    const float* pp_wo = (const float*)d_in[18], *pp_bo = (const float*)d_in[19];
    const float* pi_wq = (const float*)d_in[20], *pi_bq = (const float*)d_in[21];
    const float* pi_wk = (const float*)d_in[22], *pi_bk = (const float*)d_in[23];
    const float* pi_wv = (const float*)d_in[24], *pi_bv = (const float*)d_in[25];
    const float* pi_wo = (const float*)d_in[26], *pi_bo = (const float*)d_in[27];
    const float* ff_w1 = (const float*)d_in[28], *ff_b1 = (const float*)d_in[29];
    const float* ff_w2 = (const float*)d_in[30], *ff_b2 = (const float*)d_in[31];
    float* out = (float*)d_out;

    float *prompt0, *p1, *p2;
    __half *x, *xi, *q, *k, *v, *attn, *h, *wh;
    cudaGetSymbolAddress((void**)&prompt0, g_prompt0);
    cudaGetSymbolAddress((void**)&p1,    g_p1);
    cudaGetSymbolAddress((void**)&p2,    g_p2);
    cudaGetSymbolAddress((void**)&x,     g_x);
    cudaGetSymbolAddress((void**)&xi,    g_xi);
    cudaGetSymbolAddress((void**)&q,     g_q);
    cudaGetSymbolAddress((void**)&k,     g_k);
    cudaGetSymbolAddress((void**)&v,     g_v);
    cudaGetSymbolAddress((void**)&attn,  g_attn);
    cudaGetSymbolAddress((void**)&h,     g_h);
    cudaGetSymbolAddress((void**)&wh,    g_wh);

    __half* W[10];
    const float* srcw[10] = {pp_wq, pp_wk, pp_wv, pp_wo, pi_wq, pi_wk, pi_wv, pi_wo, ff_w1, ff_w2};
    for (int i = 0; i < 10; i++) W[i] = wh + (size_t)i * WELEM;

    cudaFuncSetAttribute(dense_gemm_kernel, cudaFuncAttributeMaxDynamicSharedMemorySize, DENSE_SMEM);
    cudaFuncSetAttribute(fattn_kernel,      cudaFuncAttributeMaxDynamicSharedMemorySize, FA_SMEM);

    // 0. all weights -> fp16, one launch
    {
        WSrc S; for (int i = 0; i < 10; i++) S.p[i] = srcw[i];
        half_w_all_kernel<<<dim3(WELEM / 4 / 256, 10), 256>>>(S, wh);
    }
    // 1. prompt0 = prompt + posp
    add4_kernel<<<(TOKP * D_MODEL / 4 + 255) / 256, 256>>>(
        (const float4*)prompt, (const float4*)posp, (float4*)prompt0, TOKP * D_MODEL / 4);
    // 2. x = LN(prompt0) -> fp16
    addln_kernel<<<TOKP, 256>>>(prompt0, nullptr, ln1g, ln1b, x);
    // 3. self QKV fused (z=3) -> fp16
    {
        DZ P = {{W[0], W[1], W[2]}, {pp_bq, pp_bk, pp_bv}, {nullptr, nullptr, nullptr},
                {nullptr, nullptr, nullptr}, {q, k, v}, {2, 2, 2}};
        dense_gemm_kernel<<<dim3(6, 32, 3), 256, DENSE_SMEM>>>(x, P, TOKP);
    }
    // 4. fused self-attention -> attn (fp16)
    fattn_kernel<<<dim3(SP / 128, NB * HEADS), 256, FA_SMEM>>>(q, k, v, attn, SP);
    // 5. p1 = attn @ Wo + bo + prompt (fp32)
    {
        DZ P = {{W[3], nullptr, nullptr}, {pp_bo, nullptr, nullptr}, {prompt, nullptr, nullptr},
                {p1, nullptr, nullptr}, {nullptr, nullptr, nullptr}, {0, 0, 0}};
        dense_gemm_kernel<<<dim3(6, 32, 1), 256, DENSE_SMEM>>>(attn, P, TOKP);
    }
    // 6. x = LN(p1 + prompt0) -> fp16
    addln_kernel<<<TOKP, 256>>>(p1, prompt0, ln2g, ln2b, x);
    // 7. xi = LN(image + posi) -> fp16
    addln_kernel<<<TOKI, 256>>>(image, posi, lnig, lnib, xi);
    // 8. cross Q -> fp16
    {
        DZ P = {{W[4], nullptr, nullptr}, {pi_bq, nullptr, nullptr}, {nullptr, nullptr, nullptr},
                {nullptr, nullptr, nullptr}, {q, nullptr, nullptr}, {2, 0, 0}};
        dense_gemm_kernel<<<dim3(6, 32, 1), 256, DENSE_SMEM>>>(x, P, TOKP);
    }
    // 9. image K,V fused (z=2) -> fp16
    {
        DZ P = {{W[5], W[6], nullptr}, {pi_bk, pi_bv, nullptr}, {nullptr, nullptr, nullptr},
                {nullptr, nullptr, nullptr}, {k, v, nullptr}, {2, 2, 0}};
        dense_gemm_kernel<<<dim3(6, 128, 2), 256, DENSE_SMEM>>>(xi, P, TOKI);
    }
    // 10. fused cross-attention -> attn (fp16)
    fattn_kernel<<<dim3(SP / 128, NB * HEADS), 256, FA_SMEM>>>(q, k, v, attn, SI);
    // 11. p2 = attn @ Wo + bo + p1 (fp32)
    {
        DZ P = {{W[7], nullptr, nullptr}, {pi_bo, nullptr, nullptr}, {p1, nullptr, nullptr},
                {p2, nullptr, nullptr}, {nullptr, nullptr, nullptr}, {0, 0, 0}};
        dense_gemm_kernel<<<dim3(6, 32, 1), 256, DENSE_SMEM>>>(attn, P, TOKP);
    }
    // 12. x = LN(p2 + prompt0) -> fp16
    addln_kernel<<<TOKP, 256>>>(p2, prompt0, ln3g, ln3b, x);
    // 13. h = relu(x @ W1 + b1) -> fp16
    {
        DZ P = {{W[8], nullptr, nullptr}, {ff_b1, nullptr, nullptr}, {nullptr, nullptr, nullptr},
                {nullptr, nullptr, nullptr}, {h, nullptr, nullptr}, {3, 0, 0}};
        dense_gemm_kernel<<<dim3(6, 32, 1), 256, DENSE_SMEM>>>(x, P, TOKP);
    }
    // 14. out = h @ W2 + b2 (fp32 final)
    {
        DZ P = {{W[9], nullptr, nullptr}, {ff_b2, nullptr, nullptr}, {nullptr, nullptr, nullptr},
                {out, nullptr, nullptr}, {nullptr, nullptr, nullptr}, {0, 0, 0}};
        dense_gemm_kernel<<<dim3(6, 32, 1), 256, DENSE_SMEM>>>(h, P, TOKP);
    }
}